// round 12
// baseline (speedup 1.0000x reference)
#include <cuda_runtime.h>
#include <cuda_bf16.h>
#include <cstdint>

#define NN   50000
#define NE   640000
#define HIDD 128
#define EF   16
#define LD2  136          // elems; 272 B row stride (K=128 tiles)
#define LDF  40           // feat tiles: 80 B row stride (K=32)
#define ME   128          // rows per CTA (pre/node kernels)
#define NT   512          // threads (pre/node kernels)
#define MEE  64           // edges per CTA (edge kernel)
#define NTE  256          // threads (edge kernel)

#define WTILE (128 * LD2)             // 17408 elems / 34816 B
#define WBYTES 34816

// ---- edge kernel smem (bytes) ----
#define OFF_WEI  0
#define OFF_B2   512
#define OFF_XW2  1024
#define OFF_B23  1536
#define OFF_DSQ  2048
#define OFF_EIJ  2304
#define OFF_RLX  2560
#define OFF_RLY  2816
#define OFF_RLZ  3072
#define OFF_DST  3328
#define OFF_SRC  3584
#define OFF_PART 3840                 // fp32[256] -> ends 4864
#define R1_OFF   5120                 // Psum -> S in place [64][LD2] bf16 (17408)
#define FA_OFF   (R1_OFF + 17408)     // feat tile [64][LDF] bf16 (5120)
#define EDGE_SMEM (FA_OFF + 5120)     // 27648

// ---- node / pre kernels ----
#define NA_OFF   1024
#define NW_OFF   (NA_OFF + WBYTES)
#define NODE_SMEM (NW_OFF + WBYTES)   // 70656

__device__ float    g_mi[(size_t)NN * HIDD];
__device__ uint32_t g_pa16[(size_t)NN * 64];   // Pa bf16-packed
__device__ uint32_t g_pb16[(size_t)NN * 64];   // Pb bf16-packed
__device__ float    g_ph[(size_t)NN * HIDD];
__device__ float    g_wei[HIDD];
__device__ float    g_b23[HIDD];
__device__ float    g_cei;
// fragment-ordered weight streams for the edge kernel:
// layout u32 index = (((ks*4 + nb)*32 + lane)*4 + nt)*2 + pair
__device__ __align__(16) uint32_t g_w2f [8 * 4 * 32 * 8];   // 8192 u32
__device__ __align__(16) uint32_t g_w23f[8 * 4 * 32 * 8];   // 8192 u32
__device__ __align__(16) uint32_t g_w1cf[2 * 4 * 32 * 8];   // 2048 u32
// [n][k] bf16 tiles for pre/node kernels:
__device__ __align__(16) __nv_bfloat16 g_w1at [WTILE];
__device__ __align__(16) __nv_bfloat16 g_w1bt [WTILE];
__device__ __align__(16) __nv_bfloat16 g_nw1at[WTILE];
__device__ __align__(16) __nv_bfloat16 g_nw1bt[WTILE];
__device__ __align__(16) __nv_bfloat16 g_nw2t [WTILE];

// ---------------------------------------------------------------------------
__device__ __forceinline__ uint32_t smem_u32(const void* p) {
    uint32_t a;
    asm("{ .reg .u64 t; cvta.to.shared.u64 t, %1; cvt.u32.u64 %0, t; }"
        : "=r"(a) : "l"(p));
    return a;
}
__device__ __forceinline__ uint32_t lds32(uint32_t a) {
    uint32_t v;
    asm volatile("ld.shared.b32 %0, [%1];" : "=r"(v) : "r"(a));
    return v;
}
__device__ __forceinline__ void sts32(uint32_t a, uint32_t v) {
    asm volatile("st.shared.b32 [%0], %1;" :: "r"(a), "r"(v));
}
__device__ __forceinline__ void sts128(uint32_t a, uint4 v) {
    asm volatile("st.shared.v4.b32 [%0], {%1,%2,%3,%4};"
                 :: "r"(a), "r"(v.x), "r"(v.y), "r"(v.z), "r"(v.w));
}
__device__ __forceinline__ void cpa16(uint32_t saddr, const void* g) {
    asm volatile("cp.async.cg.shared.global [%0], [%1], 16;"
                 :: "r"(saddr), "l"(g));
}
#define CPA_COMMIT() asm volatile("cp.async.commit_group;")
#define CPA_WAIT0()  asm volatile("cp.async.wait_group 0;" ::: "memory")

__device__ __forceinline__ uint32_t pk(float lo, float hi) {
    uint32_t l = __bfloat16_as_ushort(__float2bfloat16(lo));
    uint32_t h = __bfloat16_as_ushort(__float2bfloat16(hi));
    return l | (h << 16);
}
__device__ __forceinline__ float ubf_lo(uint32_t v) {
    return __bfloat162float(__ushort_as_bfloat16((unsigned short)(v & 0xFFFF)));
}
__device__ __forceinline__ float ubf_hi(uint32_t v) {
    return __bfloat162float(__ushort_as_bfloat16((unsigned short)(v >> 16)));
}
__device__ __forceinline__ uint32_t hadd2u(uint32_t a, uint32_t b) {
    __nv_bfloat162 r = __hadd2(*(__nv_bfloat162*)&a, *(__nv_bfloat162*)&b);
    return *(uint32_t*)&r;
}
__device__ __forceinline__ float siluf(float v) { return v / (1.f + __expf(-v)); }

__device__ __forceinline__ void mma_bf16(float* c,
                                         uint32_t a0, uint32_t a1, uint32_t a2, uint32_t a3,
                                         uint32_t b0, uint32_t b1) {
    asm volatile("mma.sync.aligned.m16n8k16.row.col.f32.bf16.bf16.f32 "
                 "{%0,%1,%2,%3}, {%4,%5,%6,%7}, {%8,%9}, {%0,%1,%2,%3};"
                 : "+f"(c[0]), "+f"(c[1]), "+f"(c[2]), "+f"(c[3])
                 : "r"(a0), "r"(a1), "r"(a2), "r"(a3), "r"(b0), "r"(b1));
}
__device__ __forceinline__ void ldsm4(uint32_t a, uint32_t& r0, uint32_t& r1,
                                      uint32_t& r2, uint32_t& r3) {
    asm volatile("ldmatrix.sync.aligned.m8n8.x4.shared.b16 {%0,%1,%2,%3}, [%4];"
                 : "=r"(r0), "=r"(r1), "=r"(r2), "=r"(r3) : "r"(a));
}

// ---- smem-B warp gemm (pre/node kernels), warp tile 32x32 ----
__device__ __forceinline__ void warp_gemm32(uint32_t aAddr, uint32_t bAddr,
                                            uint32_t ld, int ksteps, float c[2][4][4]) {
    const uint32_t mstep = 16u * ld;
#pragma unroll 2
    for (int ks = 0; ks < ksteps; ks++) {
        uint32_t A[2][4], B[2][4];
        ldsm4(aAddr,         A[0][0], A[0][1], A[0][2], A[0][3]);
        ldsm4(aAddr + mstep, A[1][0], A[1][1], A[1][2], A[1][3]);
        ldsm4(bAddr,         B[0][0], B[0][1], B[0][2], B[0][3]);
        ldsm4(bAddr + mstep, B[1][0], B[1][1], B[1][2], B[1][3]);
        aAddr += 32; bAddr += 32;
#pragma unroll
        for (int mt = 0; mt < 2; mt++)
#pragma unroll
            for (int nt = 0; nt < 4; nt++)
                mma_bf16(c[mt][nt],
                         A[mt][0], A[mt][1], A[mt][2], A[mt][3],
                         B[nt >> 1][(nt & 1) * 2], B[nt >> 1][(nt & 1) * 2 + 1]);
    }
}

// ---- LDG-B warp gemm (edge kernel): B frags streamed from global ----
__device__ __forceinline__ void warp_gemm_bldg(uint32_t aAddr, const uint4* __restrict__ bp,
                                               uint32_t ld, int ksteps, float c[2][4][4]) {
    const uint32_t mstep = 16u * ld;
#pragma unroll 2
    for (int ks = 0; ks < ksteps; ks++) {
        uint32_t A[2][4];
        uint4 B0 = __ldg(bp);
        uint4 B1 = __ldg(bp + 1);
        ldsm4(aAddr,         A[0][0], A[0][1], A[0][2], A[0][3]);
        ldsm4(aAddr + mstep, A[1][0], A[1][1], A[1][2], A[1][3]);
        aAddr += 32; bp += 256;   // 4 nb * 32 lanes * 2 uint4 per ks
#pragma unroll
        for (int mt = 0; mt < 2; mt++) {
            mma_bf16(c[mt][0], A[mt][0], A[mt][1], A[mt][2], A[mt][3], B0.x, B0.y);
            mma_bf16(c[mt][1], A[mt][0], A[mt][1], A[mt][2], A[mt][3], B0.z, B0.w);
            mma_bf16(c[mt][2], A[mt][0], A[mt][1], A[mt][2], A[mt][3], B1.x, B1.y);
            mma_bf16(c[mt][3], A[mt][0], A[mt][1], A[mt][2], A[mt][3], B1.z, B1.w);
        }
    }
}
__device__ __forceinline__ void zero_c(float c[2][4][4]) {
#pragma unroll
    for (int i = 0; i < 2; i++)
#pragma unroll
        for (int j = 0; j < 4; j++)
#pragma unroll
            for (int k = 0; k < 4; k++) c[i][j][k] = 0.f;
}

// ---------------------------------------------------------------------------
__global__ void egnn_init_kernel(const float* __restrict__ x, float* __restrict__ x_out) {
    int i = blockIdx.x * blockDim.x + threadIdx.x;
    int s = gridDim.x * blockDim.x;
    for (int j = i; j < NN * HIDD; j += s) g_mi[j] = 0.f;
    for (int j = i; j < NN * 3;   j += s) x_out[j] = x[j];
}

// ---------------------------------------------------------------------------
// prep: [n][k] tiles for pre/node; fragment streams for edge; fused vectors.
// feat weight rows permuted: k 0..15 = eattr, 16 = dsq, 17 = bias(ones).
// ---------------------------------------------------------------------------
__global__ void egnn_prep_kernel(const float* __restrict__ em_w1, const float* __restrict__ em_w2,
                                 const float* __restrict__ xm_w1, const float* __restrict__ nm_w1,
                                 const float* __restrict__ nm_w2, const float* __restrict__ em_b1,
                                 const float* __restrict__ em_b2, const float* __restrict__ ei_w,
                                 const float* __restrict__ ei_b,  const float* __restrict__ xm_b1) {
    const int T5  = 5 * WTILE;
    const int F1  = T5 + 8192;
    const int F2  = F1 + 8192;
    const int F3  = F2 + 2048;
    const int WEI = F3 + 128;
    const int B23 = WEI + 128;
    const int TOT = B23 + 1;
    int i = blockIdx.x * blockDim.x + threadIdx.x;
    int s = gridDim.x * blockDim.x;
    for (int p = i; p < TOT; p += s) {
        if (p < T5) {
            int which = p / WTILE, pl = p % WTILE;
            int n = pl / LD2, k = pl % LD2;
            float v = 0.f;
            if (k < 128) {
                switch (which) {
                    case 0: v = em_w1[(size_t)k * 128 + n]; break;
                    case 1: v = em_w1[(size_t)(128 + k) * 128 + n]; break;
                    case 2: v = nm_w1[(size_t)k * 128 + n]; break;
                    case 3: v = nm_w1[(size_t)(128 + k) * 128 + n]; break;
                    default: v = nm_w2[(size_t)k * 128 + n]; break;
                }
            }
            __nv_bfloat16* dst[5] = {g_w1at, g_w1bt, g_nw1at, g_nw1bt, g_nw2t};
            dst[which][pl] = __float2bfloat16(v);
        } else if (p < F2) {           // w2f / w23f fragment streams
            bool fused = (p >= F1);
            int pl = fused ? p - F1 : p - T5;
            int pair = pl & 1, nt = (pl >> 1) & 3, l = (pl >> 3) & 31;
            int nb = (pl >> 8) & 3, ks = pl >> 10;
            int gid = l >> 2, tig = l & 3;
            int n  = nb * 32 + nt * 8 + gid;
            int k0 = ks * 16 + tig * 2 + pair * 8;
            float v0, v1;
            if (!fused) {
                v0 = em_w2[(size_t)k0 * 128 + n];
                v1 = em_w2[(size_t)(k0 + 1) * 128 + n];
            } else {
                v0 = 0.f; v1 = 0.f;
                for (int cidx = 0; cidx < 128; cidx++) {
                    float x1 = xm_w1[(size_t)cidx * 128 + n];
                    v0 += em_w2[(size_t)k0 * 128 + cidx] * x1;
                    v1 += em_w2[(size_t)(k0 + 1) * 128 + cidx] * x1;
                }
            }
            (fused ? g_w23f : g_w2f)[pl] = pk(v0, v1);
        } else if (p < F3) {           // w1cf feat fragment stream
            int pl = p - F2;
            int pair = pl & 1, nt = (pl >> 1) & 3, l = (pl >> 3) & 31;
            int nb = (pl >> 8) & 3, ks = pl >> 10;
            int gid = l >> 2, tig = l & 3;
            int n  = nb * 32 + nt * 8 + gid;
            int k0 = ks * 16 + tig * 2 + pair * 8;
            auto fw = [&](int k) -> float {
                if (k < EF)      return em_w1[(size_t)(257 + k) * 128 + n];
                if (k == EF)     return em_w1[(size_t)256 * 128 + n];
                if (k == EF + 1) return em_b1[n];
                return 0.f;
            };
            g_w1cf[pl] = pk(fw(k0), fw(k0 + 1));
        } else if (p < WEI) {
            int k = p - F3;
            float v = 0.f;
            for (int cidx = 0; cidx < 128; cidx++)
                v += em_w2[(size_t)k * 128 + cidx] * ei_w[cidx];
            g_wei[k] = v;
        } else if (p < B23) {
            int n = p - WEI;
            float v = xm_b1[n];
            for (int cidx = 0; cidx < 128; cidx++)
                v += em_b2[cidx] * xm_w1[(size_t)cidx * 128 + n];
            g_b23[n] = v;
        } else {
            float v = ei_b[0];
            for (int cidx = 0; cidx < 128; cidx++) v += em_b2[cidx] * ei_w[cidx];
            g_cei = v;
        }
    }
}

// ---------------------------------------------------------------------------
// Precompute: Pa = h@W1a (bf16), Pb = h@W1b (bf16), Ph = h@nm_w1[128:] (fp32)
// ---------------------------------------------------------------------------
__global__ void __launch_bounds__(NT, 2) egnn_pre_kernel(const float* __restrict__ h) {
    extern __shared__ unsigned char sm[];
    const uint32_t sb = smem_u32(sm);
    const int tid  = threadIdx.x;
    const int wid  = tid >> 5;
    const int lane = tid & 31;
    const int gid  = lane >> 2;
    const int tig  = lane & 3;
    const int m0   = (wid >> 2) * 32;
    const int n0   = (wid & 3) * 32;
    const int nb   = blockIdx.x * ME;

    for (int q = tid; q < WBYTES / 16; q += NT)
        cpa16(sb + NW_OFF + q * 16, (const unsigned char*)g_w1at + q * 16);
    CPA_COMMIT();

    for (int q = tid; q < ME * 16; q += NT) {
        int e = q >> 4, ch = q & 15;
        int n = nb + e;
        uint4 w = make_uint4(0, 0, 0, 0);
        if (n < NN) {
            const float4* sp = (const float4*)(h + (size_t)n * HIDD + ch * 8);
            float4 v0 = sp[0], v1 = sp[1];
            w.x = pk(v0.x, v0.y); w.y = pk(v0.z, v0.w);
            w.z = pk(v1.x, v1.y); w.w = pk(v1.z, v1.w);
        }
        sts128(sb + NA_OFF + (uint32_t)(e * LD2 + ch * 8) * 2, w);
    }
    CPA_WAIT0();
    __syncthreads();

    const uint32_t aOff = (uint32_t)(m0 + (lane & 15)) * (LD2 * 2) + ((lane >> 4) << 4);
    const uint32_t bOff = (uint32_t)(n0 + (lane & 7) + ((lane >> 4) << 3)) * (LD2 * 2)
                        + (((lane >> 3) & 1) << 4);
    float c[2][4][4];

#pragma unroll 1
    for (int t = 0; t < 3; t++) {
        zero_c(c);
        warp_gemm32(sb + NA_OFF + aOff, sb + NW_OFF + bOff, LD2 * 2, 8, c);
        __syncthreads();
        if (t < 2) {
            const unsigned char* nw = (t == 0) ? (const unsigned char*)g_w1bt
                                               : (const unsigned char*)g_nw1bt;
            for (int q = tid; q < WBYTES / 16; q += NT)
                cpa16(sb + NW_OFF + q * 16, nw + q * 16);
            CPA_COMMIT();
        }
#pragma unroll
        for (int mt = 0; mt < 2; mt++)
#pragma unroll
            for (int nt = 0; nt < 4; nt++) {
                int row = m0 + mt * 16 + gid;
                int col = n0 + nt * 8 + tig * 2;
                float* cc = c[mt][nt];
                int na = nb + row, na2 = nb + row + 8;
                if (t < 2) {
                    uint32_t* P16 = (t == 0) ? g_pa16 : g_pb16;
                    if (na  < NN) P16[(size_t)na  * 64 + (col >> 1)] = pk(cc[0], cc[1]);
                    if (na2 < NN) P16[(size_t)na2 * 64 + (col >> 1)] = pk(cc[2], cc[3]);
                } else {
                    if (na  < NN)
                        *(float2*)(g_ph + (size_t)na  * HIDD + col) = make_float2(cc[0], cc[1]);
                    if (na2 < NN)
                        *(float2*)(g_ph + (size_t)na2 * HIDD + col) = make_float2(cc[2], cc[3]);
                }
            }
        if (t < 2) { CPA_WAIT0(); __syncthreads(); }
    }
}

// ---------------------------------------------------------------------------
// Edge kernel: 64 edges per CTA, 8 warps, 4 CTAs/SM, B frags via LDG.
// ---------------------------------------------------------------------------
__global__ void __launch_bounds__(NTE, 4) egnn_edge_kernel(
    const float* __restrict__ x,
    const int*   __restrict__ eidx,  const float* __restrict__ eattr,
    const float* __restrict__ em_b2, const float* __restrict__ xm_w2,
    float* __restrict__ x_out)
{
    extern __shared__ unsigned char sm[];
    const uint32_t sb = smem_u32(sm);
    const int tid  = threadIdx.x;
    const int wid  = tid >> 5;
    const int lane = tid & 31;
    const int gid  = lane >> 2;
    const int tig  = lane & 3;
    const int m0   = (wid >> 2) * 32;   // 0 or 32
    const int nb   = wid & 3;
    const int n0   = nb * 32;
    const int e0   = blockIdx.x * MEE;

    float* sWEI = (float*)(sm + OFF_WEI);
    float* sB2  = (float*)(sm + OFF_B2);
    float* sXW2 = (float*)(sm + OFF_XW2);
    float* sB23 = (float*)(sm + OFF_B23);
    float* sDsq = (float*)(sm + OFF_DSQ);
    float* sEij = (float*)(sm + OFF_EIJ);
    float* sRlX = (float*)(sm + OFF_RLX);
    float* sRlY = (float*)(sm + OFF_RLY);
    float* sRlZ = (float*)(sm + OFF_RLZ);
    int*   sDst = (int*)  (sm + OFF_DST);
    int*   sSrc = (int*)  (sm + OFF_SRC);
    float* sPart= (float*)(sm + OFF_PART);

    if (tid < 128) {
        sWEI[tid] = g_wei[tid]; sB2[tid] = em_b2[tid];
        sXW2[tid] = xm_w2[tid]; sB23[tid] = g_b23[tid];
    }
    if (tid < MEE) {
        int e  = e0 + tid;
        int s_ = eidx[e], d_ = eidx[NE + e];
        sSrc[tid] = s_; sDst[tid] = d_;
        float rx = x[d_ * 3 + 0] - x[s_ * 3 + 0];
        float ry = x[d_ * 3 + 1] - x[s_ * 3 + 1];
        float rz = x[d_ * 3 + 2] - x[s_ * 3 + 2];
        sRlX[tid] = rx; sRlY[tid] = ry; sRlZ[tid] = rz;
        sDsq[tid] = rx * rx + ry * ry + rz * rz;
    }
    __syncthreads();

    // gather Psum = Pa[dst] + Pb[src]  (bf16 HADD2) -> R1
    for (int q = tid; q < MEE * 8; q += NTE) {
        int e = q >> 3, ch = q & 7;
        const uint4* pa = (const uint4*)(g_pa16 + (size_t)sDst[e] * 64 + ch * 8);
        const uint4* pb = (const uint4*)(g_pb16 + (size_t)sSrc[e] * 64 + ch * 8);
        uint4 a0 = pa[0], a1 = pa[1], b0 = pb[0], b1 = pb[1];
        uint4 w0, w1;
        w0.x = hadd2u(a0.x, b0.x); w0.y = hadd2u(a0.y, b0.y);
        w0.z = hadd2u(a0.z, b0.z); w0.w = hadd2u(a0.w, b0.w);
        w1.x = hadd2u(a1.x, b1.x); w1.y = hadd2u(a1.y, b1.y);
        w1.z = hadd2u(a1.z, b1.z); w1.w = hadd2u(a1.w, b1.w);
        uint32_t base = sb + R1_OFF + (uint32_t)(e * LD2 + ch * 16) * 2;
        sts128(base, w0);
        sts128(base + 16, w1);
    }
    // feat tile [64][LDF]: cols [eattr(16) | dsq | 1 | 0]  (aligned loads)
    for (int q = tid; q < MEE * 5; q += NTE) {
        int e = q / 5, ch = q % 5;
        uint4 w = make_uint4(0, 0, 0, 0);
        if (ch < 2) {
            const float4* ap = (const float4*)(eattr + (size_t)(e0 + e) * EF + ch * 8);
            float4 v0 = ap[0], v1 = ap[1];
            w.x = pk(v0.x, v0.y); w.y = pk(v0.z, v0.w);
            w.z = pk(v1.x, v1.y); w.w = pk(v1.z, v1.w);
        } else if (ch == 2) {
            w.x = pk(sDsq[e], 1.f);
        }
        sts128(sb + FA_OFF + (uint32_t)(e * LDF + ch * 8) * 2, w);
    }
    __syncthreads();

    float c[2][4][4];
    const uint32_t aOffF = (uint32_t)(m0 + (lane & 15)) * (LDF * 2) + ((lane >> 4) << 4);
    const uint32_t aOff2 = (uint32_t)(m0 + (lane & 15)) * (LD2 * 2) + ((lane >> 4) << 4);
    const uint4* bpBase = (const uint4*)(((const uint32_t*)0) );  // placate compiler
    const int fragIdx = (nb * 32 + lane) * 2;

    // ---- feat GEMM (K=32, bias folded), B frags from g_w1cf ----
    zero_c(c);
    warp_gemm_bldg(sb + FA_OFF + aOffF, (const uint4*)g_w1cf + fragIdx, LDF * 2, 2, c);

    // ---- epilogue1: S = silu(Cfeat + Psum) in place; eij partials ----
    {
        float p[2][2] = {{0.f, 0.f}, {0.f, 0.f}};
#pragma unroll
        for (int mt = 0; mt < 2; mt++)
#pragma unroll
            for (int nt = 0; nt < 4; nt++) {
                int row = m0 + mt * 16 + gid;
                int col = n0 + nt * 8 + tig * 2;
                float* cc = c[mt][nt];
                uint32_t a0 = sb + R1_OFF + (uint32_t)(row * LD2 + col) * 2;
                uint32_t a1 = sb + R1_OFF + (uint32_t)((row + 8) * LD2 + col) * 2;
                uint32_t p0 = lds32(a0), p1 = lds32(a1);
                float s0 = siluf(cc[0] + ubf_lo(p0));
                float s1 = siluf(cc[1] + ubf_hi(p0));
                float s2 = siluf(cc[2] + ubf_lo(p1));
                float s3 = siluf(cc[3] + ubf_hi(p1));
                p[mt][0] += s0 * sWEI[col] + s1 * sWEI[col + 1];
                p[mt][1] += s2 * sWEI[col] + s3 * sWEI[col + 1];
                sts32(a0, pk(s0, s1));
                sts32(a1, pk(s2, s3));
            }
#pragma unroll
        for (int mt = 0; mt < 2; mt++)
#pragma unroll
            for (int hh = 0; hh < 2; hh++) {
                float v = p[mt][hh];
                v += __shfl_xor_sync(0xffffffffu, v, 1);
                v += __shfl_xor_sync(0xffffffffu, v, 2);
                if (tig == 0)
                    sPart[nb * 64 + m0 + mt * 16 + hh * 8 + gid] = v;
            }
    }
    __syncthreads();

    if (tid < MEE) {
        float t = sPart[tid] + sPart[64 + tid] + sPart[128 + tid] + sPart[192 + tid]
                + g_cei;
        sEij[tid] = 1.f / (1.f + __expf(-t));
    }
    __syncthreads();

    // ---- GEMM2: mij = S @ W2 (+b2); scatter (mij)*eij from registers ----
    zero_c(c);
    warp_gemm_bldg(sb + R1_OFF + aOff2, (const uint4*)g_w2f + fragIdx, LD2 * 2, 8, c);
#pragma unroll
    for (int mt = 0; mt < 2; mt++) {
        int row = m0 + mt * 16 + gid;
        int d0 = sDst[row], d1 = sDst[row + 8];
        float e0v = sEij[row], e1v = sEij[row + 8];
        float* g0 = g_mi + (size_t)d0 * HIDD;
        float* g1 = g_mi + (size_t)d1 * HIDD;
#pragma unroll
        for (int nt = 0; nt < 4; nt++) {
            int col = n0 + nt * 8 + tig * 2;
            float* cc = c[mt][nt];
            float b0 = sB2[col], b1 = sB2[col + 1];
            asm volatile("red.global.add.v2.f32 [%0], {%1,%2};"
                         :: "l"(g0 + col), "f"((cc[0] + b0) * e0v),
                            "f"((cc[1] + b1) * e0v) : "memory");
            asm volatile("red.global.add.v2.f32 [%0], {%1,%2};"
                         :: "l"(g1 + col), "f"((cc[2] + b0) * e1v),
                            "f"((cc[3] + b1) * e1v) : "memory");
        }
    }

    // ---- GEMM3': u_pre = S @ W23; gate partials ----
    zero_c(c);
    warp_gemm_bldg(sb + R1_OFF + aOff2, (const uint4*)g_w23f + fragIdx, LD2 * 2, 8, c);
    {
        float p[2][2] = {{0.f, 0.f}, {0.f, 0.f}};
#pragma unroll
        for (int mt = 0; mt < 2; mt++)
#pragma unroll
            for (int nt = 0; nt < 4; nt++) {
                int col = n0 + nt * 8 + tig * 2;
                float* cc = c[mt][nt];
                p[mt][0] += siluf(cc[0] + sB23[col]) * sXW2[col]
                          + siluf(cc[1] + sB23[col + 1]) * sXW2[col + 1];
                p[mt][1] += siluf(cc[2] + sB23[col]) * sXW2[col]
                          + siluf(cc[3] + sB23[col + 1]) * sXW2[col + 1];
            }
#pragma unroll
        for (int mt = 0; mt < 2; mt++)
#pragma unroll
            for (int hh = 0; hh < 2; hh++) {
                float v = p[mt][hh];
                v += __shfl_xor_sync(0xffffffffu, v, 1);
                v += __shfl_xor_sync(0xffffffffu, v, 2);
                if (tig == 0)
                    sPart[nb * 64 + m0 + mt * 16 + hh * 8 + gid] = v;
            }
    }
    __syncthreads();

    if (tid < MEE) {
        float g = tanhf(sPart[tid] + sPart[64 + tid] + sPart[128 + tid] + sPart[192 + tid]);
        float coef = g / (sqrtf(sDsq[tid] + 1e-8f) + 1.f);
        int d = sDst[tid];
        atomicAdd(&x_out[d * 3 + 0], sRlX[tid] * coef);
        atomicAdd(&x_out[d * 3 + 1], sRlY[tid] * coef);
        atomicAdd(&x_out[d * 3 + 2], sRlZ[tid] * coef);
    }
    (void)bpBase;
}

// ---------------------------------------------------------------------------
// Node kernel: h_out = h + nm2(silu(mi@nm_w1a + Ph + b1)) + b2
// ---------------------------------------------------------------------------
__global__ void __launch_bounds__(NT, 2) egnn_node_kernel(
    const float* __restrict__ h,
    const float* __restrict__ nm_b1, const float* __restrict__ nm_b2,
    float* __restrict__ h_out)
{
    extern __shared__ unsigned char sm[];
    const uint32_t sb = smem_u32(sm);
    const int tid  = threadIdx.x;
    const int wid  = tid >> 5;
    const int lane = tid & 31;
    const int gid  = lane >> 2;
    const int tig  = lane & 3;
    const int m0   = (wid >> 2) * 32;
    const int n0   = (wid & 3) * 32;
    const int nb   = blockIdx.x * ME;

    float* sB1 = (float*)(sm + 0);
    float* sB2 = (float*)(sm + 512);

    for (int q = tid; q < WBYTES / 16; q += NT)
        cpa16(sb + NW_OFF + q * 16, (const unsigned char*)g_nw1at + q * 16);
    CPA_COMMIT();

    if (tid < 128) { sB1[tid] = nm_b1[tid]; sB2[tid] = nm_b2[tid]; }

    for (int q = tid; q < ME * 16; q += NT) {
        int e = q >> 4, ch = q & 15;
        int n = nb + e;
        uint4 w = make_uint4(0, 0, 0, 0);
        if (n < NN) {
            const float4* sp = (const float4*)(g_mi + (size_t)n * HIDD + ch * 8);
            float4 v0 = sp[0], v1 = sp[1];
            w.x = pk(v0.x, v0.y); w.y = pk(v0.z, v0.w);
            w.z = pk(v1.x, v1.y); w.w = pk(v1.z, v1.w);
        }
        sts128(sb + NA_OFF + (uint32_t)(e * LD2 + ch * 8) * 2, w);
    }
    CPA_WAIT0();
    __syncthreads();

    const uint32_t aOff = (uint32_t)(m0 + (lane & 15)) * (LD2 * 2) + ((lane >> 4) << 4);
    const uint32_t bOff = (uint32_t)(n0 + (lane & 7) + ((lane >> 4) << 3)) * (LD2 * 2)
                        + (((lane >> 3) & 1) << 4);
    float c[2][4][4];

    zero_c(c);
    warp_gemm32(sb + NA_OFF + aOff, sb + NW_OFF + bOff, LD2 * 2, 8, c);
    __syncthreads();

    for (int q = tid; q < WBYTES / 16; q += NT)
        cpa16(sb + NW_OFF + q * 16, (const unsigned char*)g_nw2t + q * 16);
    CPA_COMMIT();

#pragma unroll
    for (int mt = 0; mt < 2; mt++)
#pragma unroll
        for (int nt = 0; nt < 4; nt++) {
            int row = m0 + mt * 16 + gid;
            int col = n0 + nt * 8 + tig * 2;
            float* cc = c[mt][nt];
            int na = nb + row, na2 = nb + row + 8;
            float2 p0 = make_float2(0.f, 0.f), p1 = make_float2(0.f, 0.f);
            if (na < NN)  p0 = *(const float2*)(g_ph + (size_t)na * HIDD + col);
            if (na2 < NN) p1 = *(const float2*)(g_ph + (size_t)na2 * HIDD + col);
            sts32(sb + NA_OFF + (uint32_t)(row * LD2 + col) * 2,
                  pk(siluf(cc[0] + p0.x + sB1[col]), siluf(cc[1] + p0.y + sB1[col + 1])));
            sts32(sb + NA_OFF + (uint32_t)((row + 8) * LD2 + col) * 2,
                  pk(siluf(cc[2] + p1.x + sB1[col]), siluf(cc[3] + p1.y + sB1[col + 1])));
        }
    CPA_WAIT0();
    __syncthreads();

    zero_c(c);
    warp_gemm32(sb + NA_OFF + aOff, sb + NW_OFF + bOff, LD2 * 2, 8, c);

#pragma unroll
    for (int mt = 0; mt < 2; mt++)
#pragma unroll
        for (int nt = 0; nt < 4; nt++) {
            int row = m0 + mt * 16 + gid;
            int col = n0 + nt * 8 + tig * 2;
            float* cc = c[mt][nt];
            int na = nb + row, na2 = nb + row + 8;
            if (na < NN) {
                const float2 hv = *(const float2*)(h + (size_t)na * HIDD + col);
                *(float2*)(h_out + (size_t)na * HIDD + col) =
                    make_float2(cc[0] + sB2[col] + hv.x, cc[1] + sB2[col + 1] + hv.y);
            }
            if (na2 < NN) {
                const float2 hv = *(const float2*)(h + (size_t)na2 * HIDD + col);
                *(float2*)(h_out + (size_t)na2 * HIDD + col) =
                    make_float2(cc[2] + sB2[col] + hv.x, cc[3] + sB2[col + 1] + hv.y);
            }
        }
}

// ---------------------------------------------------------------------------
extern "C" void kernel_launch(void* const* d_in, const int* in_sizes, int n_in,
                              void* d_out, int out_size) {
    const float* h     = (const float*)d_in[0];
    const float* x     = (const float*)d_in[1];
    const int*   eidx  = (const int*)  d_in[2];
    const float* eattr = (const float*)d_in[3];
    const float* em_w1 = (const float*)d_in[4];
    const float* em_b1 = (const float*)d_in[5];
    const float* em_w2 = (const float*)d_in[6];
    const float* em_b2 = (const float*)d_in[7];
    const float* ei_w  = (const float*)d_in[8];
    const float* ei_b  = (const float*)d_in[9];
    const float* xm_w1 = (const float*)d_in[10];
    const float* xm_b1 = (const float*)d_in[11];
    const float* xm_w2 = (const float*)d_in[12];
    const float* nm_w1 = (const float*)d_in[13];
    const float* nm_b1 = (const float*)d_in[14];
    const float* nm_w2 = (const float*)d_in[15];
    const float* nm_b2 = (const float*)d_in[16];

    float* out   = (float*)d_out;
    float* h_out = out;                        // [NN, 128]
    float* x_out = out + (size_t)NN * HIDD;    // [NN, 3]

    cudaFuncSetAttribute(egnn_edge_kernel,
                         cudaFuncAttributeMaxDynamicSharedMemorySize, EDGE_SMEM);
    cudaFuncSetAttribute(egnn_node_kernel,
                         cudaFuncAttributeMaxDynamicSharedMemorySize, NODE_SMEM);
    cudaFuncSetAttribute(egnn_pre_kernel,
                         cudaFuncAttributeMaxDynamicSharedMemorySize, NODE_SMEM);

    egnn_init_kernel<<<1024, 256>>>(x, x_out);
    egnn_prep_kernel<<<256, 256>>>(em_w1, em_w2, xm_w1, nm_w1, nm_w2,
                                   em_b1, em_b2, ei_w, ei_b, xm_b1);
    egnn_pre_kernel<<<(NN + ME - 1) / ME, NT, NODE_SMEM>>>(h);
    egnn_edge_kernel<<<NE / MEE, NTE, EDGE_SMEM>>>(
        x, eidx, eattr, em_b2, xm_w2, x_out);
    egnn_node_kernel<<<(NN + ME - 1) / ME, NT, NODE_SMEM>>>(
        h, nm_b1, nm_b2, h_out);
}

// round 15
// speedup vs baseline: 1.4413x; 1.4413x over previous
#include <cuda_runtime.h>
#include <cuda_bf16.h>
#include <cstdint>

#define NN   50000
#define NE   640000
#define HIDD 128
#define EF   16
#define LD2  136          // elems; 272 B row stride (K=128 tiles)
#define LDF  40           // feat tiles: 80 B row stride (K=32)
#define ME   128          // rows per CTA
#define NT   512          // 16 warps

#define WTILE (128 * LD2)             // 17408 elems / 34816 B
#define WBYTES 34816
#define FBYTES (128 * LDF * 2)        // 10240

// ---- edge kernel smem (bytes) ----
#define OFF_WEI  0
#define OFF_B2   512
#define OFF_XW2  1024
#define OFF_B23  1536
#define OFF_DSQ  2048
#define OFF_EIJ  2560
#define OFF_RLX  3072
#define OFF_RLY  3584
#define OFF_RLZ  4096
#define OFF_DST  4608
#define OFF_SRC  5120
#define OFF_PART 5632                 // fp32[512] -> ends 7680
#define R1_OFF   8192                 // Psum -> S in place  [128][LD2] bf16
#define RW2_OFF  (R1_OFF + WBYTES)    // W2t (preloaded at start)
#define RW23_OFF (RW2_OFF + WBYTES)   // featA+featW early, then W23t
#define FA_OFF   RW23_OFF
#define FW_OFF   (RW23_OFF + FBYTES)
#define EDGE_SMEM (RW23_OFF + WBYTES) // 112640

// ---- node / pre kernels ----
#define NA_OFF   1024
#define NW_OFF   (NA_OFF + WBYTES)
#define NODE_SMEM (NW_OFF + WBYTES)   // 70656

__device__ float    g_mi[(size_t)NN * HIDD];
__device__ uint32_t g_pa16[(size_t)NN * 64];   // Pa bf16-packed
__device__ uint32_t g_pb16[(size_t)NN * 64];   // Pb bf16-packed
__device__ float    g_ph[(size_t)NN * HIDD];
__device__ float    g_wei[HIDD];
__device__ float    g_b23[HIDD];
__device__ float    g_cei;
__device__ __align__(16) __nv_bfloat16 g_w1at [WTILE];
__device__ __align__(16) __nv_bfloat16 g_w1bt [WTILE];
__device__ __align__(16) __nv_bfloat16 g_w1ct [128 * LDF];
__device__ __align__(16) __nv_bfloat16 g_w2t  [WTILE];
__device__ __align__(16) __nv_bfloat16 g_w23t [WTILE];
__device__ __align__(16) __nv_bfloat16 g_nw1at[WTILE];
__device__ __align__(16) __nv_bfloat16 g_nw1bt[WTILE];
__device__ __align__(16) __nv_bfloat16 g_nw2t [WTILE];

// ---------------------------------------------------------------------------
__device__ __forceinline__ uint32_t smem_u32(const void* p) {
    uint32_t a;
    asm("{ .reg .u64 t; cvta.to.shared.u64 t, %1; cvt.u32.u64 %0, t; }"
        : "=r"(a) : "l"(p));
    return a;
}
__device__ __forceinline__ uint32_t lds32(uint32_t a) {
    uint32_t v;
    asm volatile("ld.shared.b32 %0, [%1];" : "=r"(v) : "r"(a));
    return v;
}
__device__ __forceinline__ void sts32(uint32_t a, uint32_t v) {
    asm volatile("st.shared.b32 [%0], %1;" :: "r"(a), "r"(v));
}
__device__ __forceinline__ void sts128(uint32_t a, uint4 v) {
    asm volatile("st.shared.v4.b32 [%0], {%1,%2,%3,%4};"
                 :: "r"(a), "r"(v.x), "r"(v.y), "r"(v.z), "r"(v.w));
}
__device__ __forceinline__ void cpa16(uint32_t saddr, const void* g) {
    asm volatile("cp.async.cg.shared.global [%0], [%1], 16;"
                 :: "r"(saddr), "l"(g));
}
#define CPA_COMMIT() asm volatile("cp.async.commit_group;")
#define CPA_WAIT0()  asm volatile("cp.async.wait_group 0;" ::: "memory")

__device__ __forceinline__ uint32_t pk(float lo, float hi) {
    uint32_t l = __bfloat16_as_ushort(__float2bfloat16(lo));
    uint32_t h = __bfloat16_as_ushort(__float2bfloat16(hi));
    return l | (h << 16);
}
__device__ __forceinline__ float ubf_lo(uint32_t v) {
    return __bfloat162float(__ushort_as_bfloat16((unsigned short)(v & 0xFFFF)));
}
__device__ __forceinline__ float ubf_hi(uint32_t v) {
    return __bfloat162float(__ushort_as_bfloat16((unsigned short)(v >> 16)));
}
__device__ __forceinline__ uint32_t hadd2u(uint32_t a, uint32_t b) {
    __nv_bfloat162 r = __hadd2(*(__nv_bfloat162*)&a, *(__nv_bfloat162*)&b);
    return *(uint32_t*)&r;
}
__device__ __forceinline__ float siluf(float v) { return v / (1.f + __expf(-v)); }

__device__ __forceinline__ void mma_bf16(float* c,
                                         uint32_t a0, uint32_t a1, uint32_t a2, uint32_t a3,
                                         uint32_t b0, uint32_t b1) {
    asm volatile("mma.sync.aligned.m16n8k16.row.col.f32.bf16.bf16.f32 "
                 "{%0,%1,%2,%3}, {%4,%5,%6,%7}, {%8,%9}, {%0,%1,%2,%3};"
                 : "+f"(c[0]), "+f"(c[1]), "+f"(c[2]), "+f"(c[3])
                 : "r"(a0), "r"(a1), "r"(a2), "r"(a3), "r"(b0), "r"(b1));
}
__device__ __forceinline__ void ldsm4(uint32_t a, uint32_t& r0, uint32_t& r1,
                                      uint32_t& r2, uint32_t& r3) {
    asm volatile("ldmatrix.sync.aligned.m8n8.x4.shared.b16 {%0,%1,%2,%3}, [%4];"
                 : "=r"(r0), "=r"(r1), "=r"(r2), "=r"(r3) : "r"(a));
}

// warp tile 32(m) x 32(n)
__device__ __forceinline__ void warp_gemm32(uint32_t aAddr, uint32_t bAddr,
                                            uint32_t ld, int ksteps, float c[2][4][4]) {
    const uint32_t mstep = 16u * ld;
#pragma unroll 2
    for (int ks = 0; ks < ksteps; ks++) {
        uint32_t A[2][4], B[2][4];
        ldsm4(aAddr,         A[0][0], A[0][1], A[0][2], A[0][3]);
        ldsm4(aAddr + mstep, A[1][0], A[1][1], A[1][2], A[1][3]);
        ldsm4(bAddr,         B[0][0], B[0][1], B[0][2], B[0][3]);
        ldsm4(bAddr + mstep, B[1][0], B[1][1], B[1][2], B[1][3]);
        aAddr += 32; bAddr += 32;
#pragma unroll
        for (int mt = 0; mt < 2; mt++)
#pragma unroll
            for (int nt = 0; nt < 4; nt++)
                mma_bf16(c[mt][nt],
                         A[mt][0], A[mt][1], A[mt][2], A[mt][3],
                         B[nt >> 1][(nt & 1) * 2], B[nt >> 1][(nt & 1) * 2 + 1]);
    }
}
__device__ __forceinline__ void zero_c(float c[2][4][4]) {
#pragma unroll
    for (int i = 0; i < 2; i++)
#pragma unroll
        for (int j = 0; j < 4; j++)
#pragma unroll
            for (int k = 0; k < 4; k++) c[i][j][k] = 0.f;
}

// ---------------------------------------------------------------------------
// prep (merged with init): weights -> bf16 transposed [n][k]; fused W23,
// w_ei, b23, c_ei; zero g_mi; x_out = x.
// Feat weight rows: k==0 = dsq, 1..16 = eattr, 17 = bias(ones).
// ---------------------------------------------------------------------------
__global__ void egnn_prep_kernel(const float* __restrict__ em_w1, const float* __restrict__ em_w2,
                                 const float* __restrict__ xm_w1, const float* __restrict__ nm_w1,
                                 const float* __restrict__ nm_w2, const float* __restrict__ em_b1,
                                 const float* __restrict__ em_b2, const float* __restrict__ ei_w,
                                 const float* __restrict__ ei_b,  const float* __restrict__ xm_b1,
                                 const float* __restrict__ x,     float* __restrict__ x_out) {
    const int E6  = 6 * WTILE;
    const int C1  = E6 + 128 * LDF;
    const int W23 = C1 + WTILE;
    const int WEI = W23 + 128;
    const int B23 = WEI + 128;
    const int TOT = B23 + 1;
    int i = blockIdx.x * blockDim.x + threadIdx.x;
    int s = gridDim.x * blockDim.x;
    // init work (overlaps with weight prep across the grid)
    for (int j = i; j < NN * HIDD; j += s) g_mi[j] = 0.f;
    for (int j = i; j < NN * 3;   j += s) x_out[j] = x[j];
    for (int p = i; p < TOT; p += s) {
        if (p < E6) {
            int which = p / WTILE, pl = p % WTILE;
            int n = pl / LD2, k = pl % LD2;
            float v = 0.f;
            if (k < 128) {
                switch (which) {
                    case 0: v = em_w1[(size_t)k * 128 + n]; break;
                    case 1: v = em_w1[(size_t)(128 + k) * 128 + n]; break;
                    case 2: v = em_w2[(size_t)k * 128 + n]; break;
                    case 3: v = nm_w1[(size_t)k * 128 + n]; break;
                    case 4: v = nm_w1[(size_t)(128 + k) * 128 + n]; break;
                    default: v = nm_w2[(size_t)k * 128 + n]; break;
                }
            }
            __nv_bfloat16* dst[6] = {g_w1at, g_w1bt, g_w2t, g_nw1at, g_nw1bt, g_nw2t};
            dst[which][pl] = __float2bfloat16(v);
        } else if (p < C1) {
            int pl = p - E6;
            int n = pl / LDF, k = pl % LDF;
            float v = 0.f;
            if (k < EF + 1)       v = em_w1[(size_t)(256 + k) * 128 + n];
            else if (k == EF + 1) v = em_b1[n];          // bias fold (ones column)
            g_w1ct[pl] = __float2bfloat16(v);
        } else if (p < W23) {
            int pl = p - C1;
            int n = pl / LD2, k = pl % LD2;
            float v = 0.f;
            if (k < 128) {
                for (int cidx = 0; cidx < 128; cidx++)
                    v += em_w2[(size_t)k * 128 + cidx] * xm_w1[(size_t)cidx * 128 + n];
            }
            g_w23t[pl] = __float2bfloat16(v);
        } else if (p < WEI) {
            int k = p - W23;
            float v = 0.f;
            for (int cidx = 0; cidx < 128; cidx++)
                v += em_w2[(size_t)k * 128 + cidx] * ei_w[cidx];
            g_wei[k] = v;
        } else if (p < B23) {
            int n = p - WEI;
            float v = xm_b1[n];
            for (int cidx = 0; cidx < 128; cidx++)
                v += em_b2[cidx] * xm_w1[(size_t)cidx * 128 + n];
            g_b23[n] = v;
        } else {
            float v = ei_b[0];
            for (int cidx = 0; cidx < 128; cidx++) v += em_b2[cidx] * ei_w[cidx];
            g_cei = v;
        }
    }
}

// ---------------------------------------------------------------------------
// Precompute: Pa = h@W1a (bf16), Pb = h@W1b (bf16), Ph = h@nm_w1[128:] (fp32)
// ---------------------------------------------------------------------------
__global__ void __launch_bounds__(NT, 2) egnn_pre_kernel(const float* __restrict__ h) {
    extern __shared__ unsigned char sm[];
    const uint32_t sb = smem_u32(sm);
    const int tid  = threadIdx.x;
    const int wid  = tid >> 5;
    const int lane = tid & 31;
    const int gid  = lane >> 2;
    const int tig  = lane & 3;
    const int m0   = (wid >> 2) * 32;
    const int n0   = (wid & 3) * 32;
    const int nb   = blockIdx.x * ME;

    for (int q = tid; q < WBYTES / 16; q += NT)
        cpa16(sb + NW_OFF + q * 16, (const unsigned char*)g_w1at + q * 16);
    CPA_COMMIT();

    for (int q = tid; q < ME * 16; q += NT) {
        int e = q >> 4, ch = q & 15;
        int n = nb + e;
        uint4 w = make_uint4(0, 0, 0, 0);
        if (n < NN) {
            const float4* sp = (const float4*)(h + (size_t)n * HIDD + ch * 8);
            float4 v0 = sp[0], v1 = sp[1];
            w.x = pk(v0.x, v0.y); w.y = pk(v0.z, v0.w);
            w.z = pk(v1.x, v1.y); w.w = pk(v1.z, v1.w);
        }
        sts128(sb + NA_OFF + (uint32_t)(e * LD2 + ch * 8) * 2, w);
    }
    CPA_WAIT0();
    __syncthreads();

    const uint32_t aOff = (uint32_t)(m0 + (lane & 15)) * (LD2 * 2) + ((lane >> 4) << 4);
    const uint32_t bOff = (uint32_t)(n0 + (lane & 7) + ((lane >> 4) << 3)) * (LD2 * 2)
                        + (((lane >> 3) & 1) << 4);
    float c[2][4][4];

#pragma unroll 1
    for (int t = 0; t < 3; t++) {
        zero_c(c);
        warp_gemm32(sb + NA_OFF + aOff, sb + NW_OFF + bOff, LD2 * 2, 8, c);
        __syncthreads();
        if (t < 2) {
            const unsigned char* nw = (t == 0) ? (const unsigned char*)g_w1bt
                                               : (const unsigned char*)g_nw1bt;
            for (int q = tid; q < WBYTES / 16; q += NT)
                cpa16(sb + NW_OFF + q * 16, nw + q * 16);
            CPA_COMMIT();
        }
#pragma unroll
        for (int mt = 0; mt < 2; mt++)
#pragma unroll
            for (int nt = 0; nt < 4; nt++) {
                int row = m0 + mt * 16 + gid;
                int col = n0 + nt * 8 + tig * 2;
                float* cc = c[mt][nt];
                int na = nb + row, na2 = nb + row + 8;
                if (t < 2) {
                    uint32_t* P16 = (t == 0) ? g_pa16 : g_pb16;
                    if (na  < NN) P16[(size_t)na  * 64 + (col >> 1)] = pk(cc[0], cc[1]);
                    if (na2 < NN) P16[(size_t)na2 * 64 + (col >> 1)] = pk(cc[2], cc[3]);
                } else {
                    if (na  < NN)
                        *(float2*)(g_ph + (size_t)na  * HIDD + col) = make_float2(cc[0], cc[1]);
                    if (na2 < NN)
                        *(float2*)(g_ph + (size_t)na2 * HIDD + col) = make_float2(cc[2], cc[3]);
                }
            }
        if (t < 2) { CPA_WAIT0(); __syncthreads(); }
    }
}

// ---------------------------------------------------------------------------
// Edge kernel: feat GEMM + epi1(S, eij) + GEMM2(scatter from regs) + GEMM3'
// ---------------------------------------------------------------------------
__global__ void __launch_bounds__(NT, 2) egnn_edge_kernel(
    const float* __restrict__ x,
    const int*   __restrict__ eidx,  const float* __restrict__ eattr,
    const float* __restrict__ em_b2, const float* __restrict__ xm_w2,
    float* __restrict__ x_out)
{
    extern __shared__ unsigned char sm[];
    const uint32_t sb = smem_u32(sm);
    const int tid  = threadIdx.x;
    const int wid  = tid >> 5;
    const int lane = tid & 31;
    const int gid  = lane >> 2;
    const int tig  = lane & 3;
    const int m0   = (wid >> 2) * 32;
    const int n0   = (wid & 3) * 32;
    const int e0   = blockIdx.x * ME;

    float* sWEI = (float*)(sm + OFF_WEI);
    float* sB2  = (float*)(sm + OFF_B2);
    float* sXW2 = (float*)(sm + OFF_XW2);
    float* sB23 = (float*)(sm + OFF_B23);
    float* sDsq = (float*)(sm + OFF_DSQ);
    float* sEij = (float*)(sm + OFF_EIJ);
    float* sRlX = (float*)(sm + OFF_RLX);
    float* sRlY = (float*)(sm + OFF_RLY);
    float* sRlZ = (float*)(sm + OFF_RLZ);
    int*   sDst = (int*)  (sm + OFF_DST);
    int*   sSrc = (int*)  (sm + OFF_SRC);
    float* sPart= (float*)(sm + OFF_PART);

    // async: feat weights + W2t (both preloaded)
    for (int q = tid; q < FBYTES / 16; q += NT)
        cpa16(sb + FW_OFF + q * 16, (const unsigned char*)g_w1ct + q * 16);
    for (int q = tid; q < WBYTES / 16; q += NT)
        cpa16(sb + RW2_OFF + q * 16, (const unsigned char*)g_w2t + q * 16);
    CPA_COMMIT();

    if (tid < 128) {
        sWEI[tid] = g_wei[tid]; sB2[tid] = em_b2[tid];
        sXW2[tid] = xm_w2[tid]; sB23[tid] = g_b23[tid];
        int e  = e0 + tid;
        int s_ = eidx[e], d_ = eidx[NE + e];
        sSrc[tid] = s_; sDst[tid] = d_;
        float rx = x[d_ * 3 + 0] - x[s_ * 3 + 0];
        float ry = x[d_ * 3 + 1] - x[s_ * 3 + 1];
        float rz = x[d_ * 3 + 2] - x[s_ * 3 + 2];
        sRlX[tid] = rx; sRlY[tid] = ry; sRlZ[tid] = rz;
        sDsq[tid] = rx * rx + ry * ry + rz * rz;
    }
    __syncthreads();

    // gather Psum = Pa[dst] + Pb[src]  (bf16 HADD2) -> R1
    for (int q = tid; q < ME * 8; q += NT) {
        int e = q >> 3, ch = q & 7;
        const uint4* pa = (const uint4*)(g_pa16 + (size_t)sDst[e] * 64 + ch * 8);
        const uint4* pb = (const uint4*)(g_pb16 + (size_t)sSrc[e] * 64 + ch * 8);
        uint4 a0 = pa[0], a1 = pa[1], b0 = pb[0], b1 = pb[1];
        uint4 w0, w1;
        w0.x = hadd2u(a0.x, b0.x); w0.y = hadd2u(a0.y, b0.y);
        w0.z = hadd2u(a0.z, b0.z); w0.w = hadd2u(a0.w, b0.w);
        w1.x = hadd2u(a1.x, b1.x); w1.y = hadd2u(a1.y, b1.y);
        w1.z = hadd2u(a1.z, b1.z); w1.w = hadd2u(a1.w, b1.w);
        uint32_t base = sb + R1_OFF + (uint32_t)(e * LD2 + ch * 16) * 2;
        sts128(base, w0);
        sts128(base + 16, w1);
    }
    // feat tile [128][LDF]: [dsq | eattr | 1(bias) | 0]
    for (int q = tid; q < ME * (LDF / 8); q += NT) {
        int e = q / (LDF / 8), ch = q % (LDF / 8);
        int c0 = ch * 8;
        float v[8];
#pragma unroll
        for (int j = 0; j < 8; j++) {
            int k = c0 + j;
            float f = 0.f;
            if (k == 0) f = sDsq[e];
            else if (k <= EF) f = eattr[(size_t)(e0 + e) * EF + (k - 1)];
            else if (k == EF + 1) f = 1.f;
            v[j] = f;
        }
        uint4 w;
        w.x = pk(v[0], v[1]); w.y = pk(v[2], v[3]);
        w.z = pk(v[4], v[5]); w.w = pk(v[6], v[7]);
        sts128(sb + FA_OFF + (uint32_t)(e * LDF + c0) * 2, w);
    }
    CPA_WAIT0();
    __syncthreads();

    float c[2][4][4];
    const uint32_t aOffF = (uint32_t)(m0 + (lane & 15)) * (LDF * 2) + ((lane >> 4) << 4);
    const uint32_t bOffF = (uint32_t)(n0 + (lane & 7) + ((lane >> 4) << 3)) * (LDF * 2)
                         + (((lane >> 3) & 1) << 4);
    const uint32_t aOff2 = (uint32_t)(m0 + (lane & 15)) * (LD2 * 2) + ((lane >> 4) << 4);
    const uint32_t bOff2 = (uint32_t)(n0 + (lane & 7) + ((lane >> 4) << 3)) * (LD2 * 2)
                         + (((lane >> 3) & 1) << 4);

    // ---- feat GEMM (K=32, bias folded) ----
    zero_c(c);
    warp_gemm32(sb + FA_OFF + aOffF, sb + FW_OFF + bOffF, LDF * 2, 2, c);
    __syncthreads();   // feat region free

    // async: W23t into RW23 (overwrites feat area)
    for (int q = tid; q < WBYTES / 16; q += NT)
        cpa16(sb + RW23_OFF + q * 16, (const unsigned char*)g_w23t + q * 16);
    CPA_COMMIT();

    // ---- epilogue1: S = silu(Cfeat + Psum) in place; eij partials (S . w_ei)
    {
        float p[2][2] = {{0.f, 0.f}, {0.f, 0.f}};
#pragma unroll
        for (int mt = 0; mt < 2; mt++)
#pragma unroll
            for (int nt = 0; nt < 4; nt++) {
                int row = m0 + mt * 16 + gid;
                int col = n0 + nt * 8 + tig * 2;
                float* cc = c[mt][nt];
                uint32_t a0 = sb + R1_OFF + (uint32_t)(row * LD2 + col) * 2;
                uint32_t a1 = sb + R1_OFF + (uint32_t)((row + 8) * LD2 + col) * 2;
                uint32_t p0 = lds32(a0), p1 = lds32(a1);
                float s0 = siluf(cc[0] + ubf_lo(p0));
                float s1 = siluf(cc[1] + ubf_hi(p0));
                float s2 = siluf(cc[2] + ubf_lo(p1));
                float s3 = siluf(cc[3] + ubf_hi(p1));
                p[mt][0] += s0 * sWEI[col] + s1 * sWEI[col + 1];
                p[mt][1] += s2 * sWEI[col] + s3 * sWEI[col + 1];
                sts32(a0, pk(s0, s1));
                sts32(a1, pk(s2, s3));
            }
#pragma unroll
        for (int mt = 0; mt < 2; mt++)
#pragma unroll
            for (int hh = 0; hh < 2; hh++) {
                float v = p[mt][hh];
                v += __shfl_xor_sync(0xffffffffu, v, 1);
                v += __shfl_xor_sync(0xffffffffu, v, 2);
                if (tig == 0)
                    sPart[(wid & 3) * 128 + m0 + mt * 16 + hh * 8 + gid] = v;
            }
    }
    __syncthreads();

    if (tid < 128) {
        float t = sPart[tid] + sPart[128 + tid] + sPart[256 + tid] + sPart[384 + tid]
                + g_cei;
        sEij[tid] = 1.f / (1.f + __expf(-t));
    }
    __syncthreads();

    // ---- GEMM2: mij = S @ W2 (+b2); scatter directly from registers ----
    zero_c(c);
    warp_gemm32(sb + R1_OFF + aOff2, sb + RW2_OFF + bOff2, LD2 * 2, 8, c);
#pragma unroll
    for (int mt = 0; mt < 2; mt++) {
        int row = m0 + mt * 16 + gid;
        int d0 = sDst[row], d1 = sDst[row + 8];
        float e0v = sEij[row], e1v = sEij[row + 8];
        float* g0 = g_mi + (size_t)d0 * HIDD;
        float* g1 = g_mi + (size_t)d1 * HIDD;
#pragma unroll
        for (int nt = 0; nt < 4; nt++) {
            int col = n0 + nt * 8 + tig * 2;
            float* cc = c[mt][nt];
            float b0 = sB2[col], b1 = sB2[col + 1];
            asm volatile("red.global.add.v2.f32 [%0], {%1,%2};"
                         :: "l"(g0 + col), "f"((cc[0] + b0) * e0v),
                            "f"((cc[1] + b1) * e0v) : "memory");
            asm volatile("red.global.add.v2.f32 [%0], {%1,%2};"
                         :: "l"(g1 + col), "f"((cc[2] + b0) * e1v),
                            "f"((cc[3] + b1) * e1v) : "memory");
        }
    }
    CPA_WAIT0();
    __syncthreads();   // W23t visible to all

    // ---- GEMM3': u_pre = S @ W23; gate partials ----
    zero_c(c);
    warp_gemm32(sb + R1_OFF + aOff2, sb + RW23_OFF + bOff2, LD2 * 2, 8, c);
    {
        float p[2][2] = {{0.f, 0.f}, {0.f, 0.f}};
#pragma unroll
        for (int mt = 0; mt < 2; mt++)
#pragma unroll
            for (int nt = 0; nt < 4; nt++) {
                int col = n0 + nt * 8 + tig * 2;
                float* cc = c[mt][nt];
                p[mt][0] += siluf(cc[0] + sB23[col]) * sXW2[col]
                          + siluf(cc[1] + sB23[col + 1]) * sXW2[col + 1];
                p[mt][1] += siluf(cc[2] + sB23[col]) * sXW2[col]
                          + siluf(cc[3] + sB23[col + 1]) * sXW2[col + 1];
            }
#pragma unroll
        for (int mt = 0; mt < 2; mt++)
#pragma unroll
            for (int hh = 0; hh < 2; hh++) {
                float v = p[mt][hh];
                v += __shfl_xor_sync(0xffffffffu, v, 1);
                v += __shfl_xor_sync(0xffffffffu, v, 2);
                if (tig == 0)
                    sPart[(wid & 3) * 128 + m0 + mt * 16 + hh * 8 + gid] = v;
            }
    }
    __syncthreads();

    if (tid < 128) {
        float g = tanhf(sPart[tid] + sPart[128 + tid] + sPart[256 + tid] + sPart[384 + tid]);
        float coef = g / (sqrtf(sDsq[tid] + 1e-8f) + 1.f);
        int d = sDst[tid];
        atomicAdd(&x_out[d * 3 + 0], sRlX[tid] * coef);
        atomicAdd(&x_out[d * 3 + 1], sRlY[tid] * coef);
        atomicAdd(&x_out[d * 3 + 2], sRlZ[tid] * coef);
    }
}

// ---------------------------------------------------------------------------
// Node kernel: h_out = h + nm2(silu(mi@nm_w1a + Ph + b1)) + b2
// ---------------------------------------------------------------------------
__global__ void __launch_bounds__(NT, 2) egnn_node_kernel(
    const float* __restrict__ h,
    const float* __restrict__ nm_b1, const float* __restrict__ nm_b2,
    float* __restrict__ h_out)
{
    extern __shared__ unsigned char sm[];
    const uint32_t sb = smem_u32(sm);
    const int tid  = threadIdx.x;
    const int wid  = tid >> 5;
    const int lane = tid & 31;
    const int gid  = lane >> 2;
    const int tig  = lane & 3;
    const int m0   = (wid >> 2) * 32;
    const int n0   = (wid & 3) * 32;
    const int nb   = blockIdx.x * ME;

    float* sB1 = (float*)(sm + 0);
    float* sB2 = (float*)(sm + 512);

    for (int q = tid; q < WBYTES / 16; q += NT)
        cpa16(sb + NW_OFF + q * 16, (const unsigned char*)g_nw1at + q * 16);
    CPA_COMMIT();

    if (tid < 128) { sB1[tid] = nm_b1[tid]; sB2[tid] = nm_b2[tid]; }

    for (int q = tid; q < ME * 16; q += NT) {
        int e = q >> 4, ch = q & 15;
        int n = nb + e;
        uint4 w = make_uint4(0, 0, 0, 0);
        if (n < NN) {
            const float4* sp = (const float4*)(g_mi + (size_t)n * HIDD + ch * 8);
            float4 v0 = sp[0], v1 = sp[1];
            w.x = pk(v0.x, v0.y); w.y = pk(v0.z, v0.w);
            w.z = pk(v1.x, v1.y); w.w = pk(v1.z, v1.w);
        }
        sts128(sb + NA_OFF + (uint32_t)(e * LD2 + ch * 8) * 2, w);
    }
    CPA_WAIT0();
    __syncthreads();

    const uint32_t aOff = (uint32_t)(m0 + (lane & 15)) * (LD2 * 2) + ((lane >> 4) << 4);
    const uint32_t bOff = (uint32_t)(n0 + (lane & 7) + ((lane >> 4) << 3)) * (LD2 * 2)
                        + (((lane >> 3) & 1) << 4);
    float c[2][4][4];

    zero_c(c);
    warp_gemm32(sb + NA_OFF + aOff, sb + NW_OFF + bOff, LD2 * 2, 8, c);
    __syncthreads();

    for (int q = tid; q < WBYTES / 16; q += NT)
        cpa16(sb + NW_OFF + q * 16, (const unsigned char*)g_nw2t + q * 16);
    CPA_COMMIT();

#pragma unroll
    for (int mt = 0; mt < 2; mt++)
#pragma unroll
        for (int nt = 0; nt < 4; nt++) {
            int row = m0 + mt * 16 + gid;
            int col = n0 + nt * 8 + tig * 2;
            float* cc = c[mt][nt];
            int na = nb + row, na2 = nb + row + 8;
            float2 p0 = make_float2(0.f, 0.f), p1 = make_float2(0.f, 0.f);
            if (na < NN)  p0 = *(const float2*)(g_ph + (size_t)na * HIDD + col);
            if (na2 < NN) p1 = *(const float2*)(g_ph + (size_t)na2 * HIDD + col);
            sts32(sb + NA_OFF + (uint32_t)(row * LD2 + col) * 2,
                  pk(siluf(cc[0] + p0.x + sB1[col]), siluf(cc[1] + p0.y + sB1[col + 1])));
            sts32(sb + NA_OFF + (uint32_t)((row + 8) * LD2 + col) * 2,
                  pk(siluf(cc[2] + p1.x + sB1[col]), siluf(cc[3] + p1.y + sB1[col + 1])));
        }
    CPA_WAIT0();
    __syncthreads();

    zero_c(c);
    warp_gemm32(sb + NA_OFF + aOff, sb + NW_OFF + bOff, LD2 * 2, 8, c);

#pragma unroll
    for (int mt = 0; mt < 2; mt++)
#pragma unroll
        for (int nt = 0; nt < 4; nt++) {
            int row = m0 + mt * 16 + gid;
            int col = n0 + nt * 8 + tig * 2;
            float* cc = c[mt][nt];
            int na = nb + row, na2 = nb + row + 8;
            if (na < NN) {
                const float2 hv = *(const float2*)(h + (size_t)na * HIDD + col);
                *(float2*)(h_out + (size_t)na * HIDD + col) =
                    make_float2(cc[0] + sB2[col] + hv.x, cc[1] + sB2[col + 1] + hv.y);
            }
            if (na2 < NN) {
                const float2 hv = *(const float2*)(h + (size_t)na2 * HIDD + col);
                *(float2*)(h_out + (size_t)na2 * HIDD + col) =
                    make_float2(cc[2] + sB2[col] + hv.x, cc[3] + sB2[col + 1] + hv.y);
            }
        }
}

// ---------------------------------------------------------------------------
extern "C" void kernel_launch(void* const* d_in, const int* in_sizes, int n_in,
                              void* d_out, int out_size) {
    const float* h     = (const float*)d_in[0];
    const float* x     = (const float*)d_in[1];
    const int*   eidx  = (const int*)  d_in[2];
    const float* eattr = (const float*)d_in[3];
    const float* em_w1 = (const float*)d_in[4];
    const float* em_b1 = (const float*)d_in[5];
    const float* em_w2 = (const float*)d_in[6];
    const float* em_b2 = (const float*)d_in[7];
    const float* ei_w  = (const float*)d_in[8];
    const float* ei_b  = (const float*)d_in[9];
    const float* xm_w1 = (const float*)d_in[10];
    const float* xm_b1 = (const float*)d_in[11];
    const float* xm_w2 = (const float*)d_in[12];
    const float* nm_w1 = (const float*)d_in[13];
    const float* nm_b1 = (const float*)d_in[14];
    const float* nm_w2 = (const float*)d_in[15];
    const float* nm_b2 = (const float*)d_in[16];

    float* out   = (float*)d_out;
    float* h_out = out;                        // [NN, 128]
    float* x_out = out + (size_t)NN * HIDD;    // [NN, 3]

    cudaFuncSetAttribute(egnn_edge_kernel,
                         cudaFuncAttributeMaxDynamicSharedMemorySize, EDGE_SMEM);
    cudaFuncSetAttribute(egnn_node_kernel,
                         cudaFuncAttributeMaxDynamicSharedMemorySize, NODE_SMEM);
    cudaFuncSetAttribute(egnn_pre_kernel,
                         cudaFuncAttributeMaxDynamicSharedMemorySize, NODE_SMEM);

    egnn_prep_kernel<<<592, 256>>>(em_w1, em_w2, xm_w1, nm_w1, nm_w2,
                                   em_b1, em_b2, ei_w, ei_b, xm_b1, x, x_out);
    egnn_pre_kernel<<<(NN + ME - 1) / ME, NT, NODE_SMEM>>>(h);
    egnn_edge_kernel<<<NE / ME, NT, EDGE_SMEM>>>(
        x, eidx, eattr, em_b2, xm_w2, x_out);
    egnn_node_kernel<<<(NN + ME - 1) / ME, NT, NODE_SMEM>>>(
        h, nm_b1, nm_b2, h_out);
}

// round 17
// speedup vs baseline: 1.4481x; 1.0047x over previous
#include <cuda_runtime.h>
#include <cuda_bf16.h>
#include <cstdint>

#define NN   50000
#define NE   640000
#define HIDD 128
#define EF   16
#define LD2  136          // elems; 272 B row stride (K=128 tiles)
#define LDF  40           // feat tiles: 80 B row stride (K=32)
#define ME   128          // rows per CTA
#define NT   512          // 16 warps

#define WTILE (128 * LD2)             // 17408 elems / 34816 B
#define WBYTES 34816
#define FBYTES (128 * LDF * 2)        // 10240

// ---- edge kernel smem (bytes) ----
#define OFF_WEI  0
#define OFF_B2   512
#define OFF_XW2  1024
#define OFF_B23  1536
#define OFF_DSQ  2048
#define OFF_EIJ  2560
#define OFF_RLX  3072
#define OFF_RLY  3584
#define OFF_RLZ  4096
#define OFF_DST  4608
#define OFF_SRC  5120
#define OFF_PART 5632                 // fp32[512] -> ends 7680
#define R1_OFF   8192                 // Psum -> S in place  [128][LD2] bf16
#define RW2_OFF  (R1_OFF + WBYTES)    // W2t (preloaded at start)
#define RW23_OFF (RW2_OFF + WBYTES)   // featA+featW early, then W23t
#define FA_OFF   RW23_OFF
#define FW_OFF   (RW23_OFF + FBYTES)
#define EDGE_SMEM (RW23_OFF + WBYTES) // 112640

// ---- node / pre kernels ----
#define NA_OFF   1024
#define NW_OFF   (NA_OFF + WBYTES)
#define NODE_SMEM (NW_OFF + WBYTES)   // 70656

__device__ float    g_mi[(size_t)NN * HIDD];
__device__ uint32_t g_pa16[(size_t)NN * 64];   // Pa bf16-packed
__device__ uint32_t g_pb16[(size_t)NN * 64];   // Pb bf16-packed
__device__ uint32_t g_ph16[(size_t)NN * 64];   // Ph bf16-packed
__device__ float    g_wei[HIDD];
__device__ float    g_b23[HIDD];
__device__ float    g_cei;
__device__ __align__(16) __nv_bfloat16 g_w1at [WTILE];
__device__ __align__(16) __nv_bfloat16 g_w1bt [WTILE];
__device__ __align__(16) __nv_bfloat16 g_w1ct [128 * LDF];
__device__ __align__(16) __nv_bfloat16 g_w2t  [WTILE];
__device__ __align__(16) __nv_bfloat16 g_w23t [WTILE];
__device__ __align__(16) __nv_bfloat16 g_nw1at[WTILE];
__device__ __align__(16) __nv_bfloat16 g_nw1bt[WTILE];
__device__ __align__(16) __nv_bfloat16 g_nw2t [WTILE];

// ---------------------------------------------------------------------------
__device__ __forceinline__ uint32_t smem_u32(const void* p) {
    uint32_t a;
    asm("{ .reg .u64 t; cvta.to.shared.u64 t, %1; cvt.u32.u64 %0, t; }"
        : "=r"(a) : "l"(p));
    return a;
}
__device__ __forceinline__ uint32_t lds32(uint32_t a) {
    uint32_t v;
    asm volatile("ld.shared.b32 %0, [%1];" : "=r"(v) : "r"(a));
    return v;
}
__device__ __forceinline__ void sts32(uint32_t a, uint32_t v) {
    asm volatile("st.shared.b32 [%0], %1;" :: "r"(a), "r"(v));
}
__device__ __forceinline__ void sts128(uint32_t a, uint4 v) {
    asm volatile("st.shared.v4.b32 [%0], {%1,%2,%3,%4};"
                 :: "r"(a), "r"(v.x), "r"(v.y), "r"(v.z), "r"(v.w));
}
__device__ __forceinline__ void cpa16(uint32_t saddr, const void* g) {
    asm volatile("cp.async.cg.shared.global [%0], [%1], 16;"
                 :: "r"(saddr), "l"(g));
}
#define CPA_COMMIT() asm volatile("cp.async.commit_group;")
#define CPA_WAIT0()  asm volatile("cp.async.wait_group 0;" ::: "memory")

__device__ __forceinline__ uint32_t pk(float lo, float hi) {
    uint32_t l = __bfloat16_as_ushort(__float2bfloat16(lo));
    uint32_t h = __bfloat16_as_ushort(__float2bfloat16(hi));
    return l | (h << 16);
}
__device__ __forceinline__ float ubf_lo(uint32_t v) {
    return __bfloat162float(__ushort_as_bfloat16((unsigned short)(v & 0xFFFF)));
}
__device__ __forceinline__ float ubf_hi(uint32_t v) {
    return __bfloat162float(__ushort_as_bfloat16((unsigned short)(v >> 16)));
}
__device__ __forceinline__ uint32_t hadd2u(uint32_t a, uint32_t b) {
    __nv_bfloat162 r = __hadd2(*(__nv_bfloat162*)&a, *(__nv_bfloat162*)&b);
    return *(uint32_t*)&r;
}
__device__ __forceinline__ float siluf(float v) { return v / (1.f + __expf(-v)); }

__device__ __forceinline__ void mma_bf16(float* c,
                                         uint32_t a0, uint32_t a1, uint32_t a2, uint32_t a3,
                                         uint32_t b0, uint32_t b1) {
    asm volatile("mma.sync.aligned.m16n8k16.row.col.f32.bf16.bf16.f32 "
                 "{%0,%1,%2,%3}, {%4,%5,%6,%7}, {%8,%9}, {%0,%1,%2,%3};"
                 : "+f"(c[0]), "+f"(c[1]), "+f"(c[2]), "+f"(c[3])
                 : "r"(a0), "r"(a1), "r"(a2), "r"(a3), "r"(b0), "r"(b1));
}
__device__ __forceinline__ void ldsm4(uint32_t a, uint32_t& r0, uint32_t& r1,
                                      uint32_t& r2, uint32_t& r3) {
    asm volatile("ldmatrix.sync.aligned.m8n8.x4.shared.b16 {%0,%1,%2,%3}, [%4];"
                 : "=r"(r0), "=r"(r1), "=r"(r2), "=r"(r3) : "r"(a));
}

// warp tile 32(m) x 32(n)
__device__ __forceinline__ void warp_gemm32(uint32_t aAddr, uint32_t bAddr,
                                            uint32_t ld, int ksteps, float c[2][4][4]) {
    const uint32_t mstep = 16u * ld;
#pragma unroll 2
    for (int ks = 0; ks < ksteps; ks++) {
        uint32_t A[2][4], B[2][4];
        ldsm4(aAddr,         A[0][0], A[0][1], A[0][2], A[0][3]);
        ldsm4(aAddr + mstep, A[1][0], A[1][1], A[1][2], A[1][3]);
        ldsm4(bAddr,         B[0][0], B[0][1], B[0][2], B[0][3]);
        ldsm4(bAddr + mstep, B[1][0], B[1][1], B[1][2], B[1][3]);
        aAddr += 32; bAddr += 32;
#pragma unroll
        for (int mt = 0; mt < 2; mt++)
#pragma unroll
            for (int nt = 0; nt < 4; nt++)
                mma_bf16(c[mt][nt],
                         A[mt][0], A[mt][1], A[mt][2], A[mt][3],
                         B[nt >> 1][(nt & 1) * 2], B[nt >> 1][(nt & 1) * 2 + 1]);
    }
}
__device__ __forceinline__ void zero_c(float c[2][4][4]) {
#pragma unroll
    for (int i = 0; i < 2; i++)
#pragma unroll
        for (int j = 0; j < 4; j++)
#pragma unroll
            for (int k = 0; k < 4; k++) c[i][j][k] = 0.f;
}

// ---------------------------------------------------------------------------
// prep (merged with init): weights -> bf16 transposed [n][k]; fused W23,
// w_ei, b23, c_ei; zero g_mi; x_out = x.
// Feat weight rows PERMUTED: k 0..15 = eattr, 16 = dsq, 17 = bias(ones).
// ---------------------------------------------------------------------------
__global__ void egnn_prep_kernel(const float* __restrict__ em_w1, const float* __restrict__ em_w2,
                                 const float* __restrict__ xm_w1, const float* __restrict__ nm_w1,
                                 const float* __restrict__ nm_w2, const float* __restrict__ em_b1,
                                 const float* __restrict__ em_b2, const float* __restrict__ ei_w,
                                 const float* __restrict__ ei_b,  const float* __restrict__ xm_b1,
                                 const float* __restrict__ x,     float* __restrict__ x_out) {
    const int E6  = 6 * WTILE;
    const int C1  = E6 + 128 * LDF;
    const int W23 = C1 + WTILE;
    const int WEI = W23 + 128;
    const int B23 = WEI + 128;
    const int TOT = B23 + 1;
    int i = blockIdx.x * blockDim.x + threadIdx.x;
    int s = gridDim.x * blockDim.x;
    // init work (overlaps with weight prep across the grid)
    for (int j = i; j < NN * HIDD; j += s) g_mi[j] = 0.f;
    for (int j = i; j < NN * 3;   j += s) x_out[j] = x[j];
    for (int p = i; p < TOT; p += s) {
        if (p < E6) {
            int which = p / WTILE, pl = p % WTILE;
            int n = pl / LD2, k = pl % LD2;
            float v = 0.f;
            if (k < 128) {
                switch (which) {
                    case 0: v = em_w1[(size_t)k * 128 + n]; break;
                    case 1: v = em_w1[(size_t)(128 + k) * 128 + n]; break;
                    case 2: v = em_w2[(size_t)k * 128 + n]; break;
                    case 3: v = nm_w1[(size_t)k * 128 + n]; break;
                    case 4: v = nm_w1[(size_t)(128 + k) * 128 + n]; break;
                    default: v = nm_w2[(size_t)k * 128 + n]; break;
                }
            }
            __nv_bfloat16* dst[6] = {g_w1at, g_w1bt, g_w2t, g_nw1at, g_nw1bt, g_nw2t};
            dst[which][pl] = __float2bfloat16(v);
        } else if (p < C1) {
            int pl = p - E6;
            int n = pl / LDF, k = pl % LDF;
            float v = 0.f;
            if (k < EF)           v = em_w1[(size_t)(257 + k) * 128 + n]; // eattr rows
            else if (k == EF)     v = em_w1[(size_t)256 * 128 + n];       // dsq row
            else if (k == EF + 1) v = em_b1[n];                           // bias fold
            g_w1ct[pl] = __float2bfloat16(v);
        } else if (p < W23) {
            int pl = p - C1;
            int n = pl / LD2, k = pl % LD2;
            float v = 0.f;
            if (k < 128) {
                for (int cidx = 0; cidx < 128; cidx++)
                    v += em_w2[(size_t)k * 128 + cidx] * xm_w1[(size_t)cidx * 128 + n];
            }
            g_w23t[pl] = __float2bfloat16(v);
        } else if (p < WEI) {
            int k = p - W23;
            float v = 0.f;
            for (int cidx = 0; cidx < 128; cidx++)
                v += em_w2[(size_t)k * 128 + cidx] * ei_w[cidx];
            g_wei[k] = v;
        } else if (p < B23) {
            int n = p - WEI;
            float v = xm_b1[n];
            for (int cidx = 0; cidx < 128; cidx++)
                v += em_b2[cidx] * xm_w1[(size_t)cidx * 128 + n];
            g_b23[n] = v;
        } else {
            float v = ei_b[0];
            for (int cidx = 0; cidx < 128; cidx++) v += em_b2[cidx] * ei_w[cidx];
            g_cei = v;
        }
    }
}

// ---------------------------------------------------------------------------
// Precompute: Pa = h@W1a, Pb = h@W1b, Ph = h@nm_w1[128:]  (all bf16-packed)
// ---------------------------------------------------------------------------
__global__ void __launch_bounds__(NT, 2) egnn_pre_kernel(const float* __restrict__ h) {
    extern __shared__ unsigned char sm[];
    const uint32_t sb = smem_u32(sm);
    const int tid  = threadIdx.x;
    const int wid  = tid >> 5;
    const int lane = tid & 31;
    const int gid  = lane >> 2;
    const int tig  = lane & 3;
    const int m0   = (wid >> 2) * 32;
    const int n0   = (wid & 3) * 32;
    const int nb   = blockIdx.x * ME;

    for (int q = tid; q < WBYTES / 16; q += NT)
        cpa16(sb + NW_OFF + q * 16, (const unsigned char*)g_w1at + q * 16);
    CPA_COMMIT();

    for (int q = tid; q < ME * 16; q += NT) {
        int e = q >> 4, ch = q & 15;
        int n = nb + e;
        uint4 w = make_uint4(0, 0, 0, 0);
        if (n < NN) {
            const float4* sp = (const float4*)(h + (size_t)n * HIDD + ch * 8);
            float4 v0 = sp[0], v1 = sp[1];
            w.x = pk(v0.x, v0.y); w.y = pk(v0.z, v0.w);
            w.z = pk(v1.x, v1.y); w.w = pk(v1.z, v1.w);
        }
        sts128(sb + NA_OFF + (uint32_t)(e * LD2 + ch * 8) * 2, w);
    }
    CPA_WAIT0();
    __syncthreads();

    const uint32_t aOff = (uint32_t)(m0 + (lane & 15)) * (LD2 * 2) + ((lane >> 4) << 4);
    const uint32_t bOff = (uint32_t)(n0 + (lane & 7) + ((lane >> 4) << 3)) * (LD2 * 2)
                        + (((lane >> 3) & 1) << 4);
    float c[2][4][4];

#pragma unroll 1
    for (int t = 0; t < 3; t++) {
        zero_c(c);
        warp_gemm32(sb + NA_OFF + aOff, sb + NW_OFF + bOff, LD2 * 2, 8, c);
        __syncthreads();
        if (t < 2) {
            const unsigned char* nw = (t == 0) ? (const unsigned char*)g_w1bt
                                               : (const unsigned char*)g_nw1bt;
            for (int q = tid; q < WBYTES / 16; q += NT)
                cpa16(sb + NW_OFF + q * 16, nw + q * 16);
            CPA_COMMIT();
        }
        uint32_t* P16 = (t == 0) ? g_pa16 : (t == 1) ? g_pb16 : g_ph16;
#pragma unroll
        for (int mt = 0; mt < 2; mt++)
#pragma unroll
            for (int nt = 0; nt < 4; nt++) {
                int row = m0 + mt * 16 + gid;
                int col = n0 + nt * 8 + tig * 2;
                float* cc = c[mt][nt];
                int na = nb + row, na2 = nb + row + 8;
                if (na  < NN) P16[(size_t)na  * 64 + (col >> 1)] = pk(cc[0], cc[1]);
                if (na2 < NN) P16[(size_t)na2 * 64 + (col >> 1)] = pk(cc[2], cc[3]);
            }
        if (t < 2) { CPA_WAIT0(); __syncthreads(); }
    }
}

// ---------------------------------------------------------------------------
// Edge kernel: feat GEMM + epi1(S, eij) + GEMM2(scatter from regs) + GEMM3'
// ---------------------------------------------------------------------------
__global__ void __launch_bounds__(NT, 2) egnn_edge_kernel(
    const float* __restrict__ x,
    const int*   __restrict__ eidx,  const float* __restrict__ eattr,
    const float* __restrict__ em_b2, const float* __restrict__ xm_w2,
    float* __restrict__ x_out)
{
    extern __shared__ unsigned char sm[];
    const uint32_t sb = smem_u32(sm);
    const int tid  = threadIdx.x;
    const int wid  = tid >> 5;
    const int lane = tid & 31;
    const int gid  = lane >> 2;
    const int tig  = lane & 3;
    const int m0   = (wid >> 2) * 32;
    const int n0   = (wid & 3) * 32;
    const int e0   = blockIdx.x * ME;

    float* sWEI = (float*)(sm + OFF_WEI);
    float* sB2  = (float*)(sm + OFF_B2);
    float* sXW2 = (float*)(sm + OFF_XW2);
    float* sB23 = (float*)(sm + OFF_B23);
    float* sDsq = (float*)(sm + OFF_DSQ);
    float* sEij = (float*)(sm + OFF_EIJ);
    float* sRlX = (float*)(sm + OFF_RLX);
    float* sRlY = (float*)(sm + OFF_RLY);
    float* sRlZ = (float*)(sm + OFF_RLZ);
    int*   sDst = (int*)  (sm + OFF_DST);
    int*   sSrc = (int*)  (sm + OFF_SRC);
    float* sPart= (float*)(sm + OFF_PART);

    // async: feat weights + W2t (both preloaded)
    for (int q = tid; q < FBYTES / 16; q += NT)
        cpa16(sb + FW_OFF + q * 16, (const unsigned char*)g_w1ct + q * 16);
    for (int q = tid; q < WBYTES / 16; q += NT)
        cpa16(sb + RW2_OFF + q * 16, (const unsigned char*)g_w2t + q * 16);
    CPA_COMMIT();

    if (tid < 128) {
        sWEI[tid] = g_wei[tid]; sB2[tid] = em_b2[tid];
        sXW2[tid] = xm_w2[tid]; sB23[tid] = g_b23[tid];
        int e  = e0 + tid;
        int s_ = eidx[e], d_ = eidx[NE + e];
        sSrc[tid] = s_; sDst[tid] = d_;
        float rx = x[d_ * 3 + 0] - x[s_ * 3 + 0];
        float ry = x[d_ * 3 + 1] - x[s_ * 3 + 1];
        float rz = x[d_ * 3 + 2] - x[s_ * 3 + 2];
        sRlX[tid] = rx; sRlY[tid] = ry; sRlZ[tid] = rz;
        sDsq[tid] = rx * rx + ry * ry + rz * rz;
    }
    __syncthreads();

    // gather Psum = Pa[dst] + Pb[src]  (bf16 HADD2) -> R1
    for (int q = tid; q < ME * 8; q += NT) {
        int e = q >> 3, ch = q & 7;
        const uint4* pa = (const uint4*)(g_pa16 + (size_t)sDst[e] * 64 + ch * 8);
        const uint4* pb = (const uint4*)(g_pb16 + (size_t)sSrc[e] * 64 + ch * 8);
        uint4 a0 = pa[0], a1 = pa[1], b0 = pb[0], b1 = pb[1];
        uint4 w0, w1;
        w0.x = hadd2u(a0.x, b0.x); w0.y = hadd2u(a0.y, b0.y);
        w0.z = hadd2u(a0.z, b0.z); w0.w = hadd2u(a0.w, b0.w);
        w1.x = hadd2u(a1.x, b1.x); w1.y = hadd2u(a1.y, b1.y);
        w1.z = hadd2u(a1.z, b1.z); w1.w = hadd2u(a1.w, b1.w);
        uint32_t base = sb + R1_OFF + (uint32_t)(e * LD2 + ch * 16) * 2;
        sts128(base, w0);
        sts128(base + 16, w1);
    }
    // feat tile [128][LDF]: cols [eattr(16) | dsq | 1 | 0]  (aligned loads)
    for (int q = tid; q < ME * 5; q += NT) {
        int e = q / 5, ch = q % 5;
        uint4 w = make_uint4(0, 0, 0, 0);
        if (ch < 2) {
            const float4* ap = (const float4*)(eattr + (size_t)(e0 + e) * EF + ch * 8);
            float4 v0 = ap[0], v1 = ap[1];
            w.x = pk(v0.x, v0.y); w.y = pk(v0.z, v0.w);
            w.z = pk(v1.x, v1.y); w.w = pk(v1.z, v1.w);
        } else if (ch == 2) {
            w.x = pk(sDsq[e], 1.f);
        }
        sts128(sb + FA_OFF + (uint32_t)(e * LDF + ch * 8) * 2, w);
    }
    CPA_WAIT0();
    __syncthreads();

    float c[2][4][4];
    const uint32_t aOffF = (uint32_t)(m0 + (lane & 15)) * (LDF * 2) + ((lane >> 4) << 4);
    const uint32_t bOffF = (uint32_t)(n0 + (lane & 7) + ((lane >> 4) << 3)) * (LDF * 2)
                         + (((lane >> 3) & 1) << 4);
    const uint32_t aOff2 = (uint32_t)(m0 + (lane & 15)) * (LD2 * 2) + ((lane >> 4) << 4);
    const uint32_t bOff2 = (uint32_t)(n0 + (lane & 7) + ((lane >> 4) << 3)) * (LD2 * 2)
                         + (((lane >> 3) & 1) << 4);

    // ---- feat GEMM (K=32, bias folded) ----
    zero_c(c);
    warp_gemm32(sb + FA_OFF + aOffF, sb + FW_OFF + bOffF, LDF * 2, 2, c);
    __syncthreads();   // feat region free

    // async: W23t into RW23 (overwrites feat area)
    for (int q = tid; q < WBYTES / 16; q += NT)
        cpa16(sb + RW23_OFF + q * 16, (const unsigned char*)g_w23t + q * 16);
    CPA_COMMIT();

    // ---- epilogue1: S = silu(Cfeat + Psum) in place; eij partials (S . w_ei)
    {
        float p[2][2] = {{0.f, 0.f}, {0.f, 0.f}};
#pragma unroll
        for (int mt = 0; mt < 2; mt++)
#pragma unroll
            for (int nt = 0; nt < 4; nt++) {
                int row = m0 + mt * 16 + gid;
                int col = n0 + nt * 8 + tig * 2;
                float* cc = c[mt][nt];
                uint32_t a0 = sb + R1_OFF + (uint32_t)(row * LD2 + col) * 2;
                uint32_t a1 = sb + R1_OFF + (uint32_t)((row + 8) * LD2 + col) * 2;
                uint32_t p0 = lds32(a0), p1 = lds32(a1);
                float s0 = siluf(cc[0] + ubf_lo(p0));
                float s1 = siluf(cc[1] + ubf_hi(p0));
                float s2 = siluf(cc[2] + ubf_lo(p1));
                float s3 = siluf(cc[3] + ubf_hi(p1));
                p[mt][0] += s0 * sWEI[col] + s1 * sWEI[col + 1];
                p[mt][1] += s2 * sWEI[col] + s3 * sWEI[col + 1];
                sts32(a0, pk(s0, s1));
                sts32(a1, pk(s2, s3));
            }
#pragma unroll
        for (int mt = 0; mt < 2; mt++)
#pragma unroll
            for (int hh = 0; hh < 2; hh++) {
                float v = p[mt][hh];
                v += __shfl_xor_sync(0xffffffffu, v, 1);
                v += __shfl_xor_sync(0xffffffffu, v, 2);
                if (tig == 0)
                    sPart[(wid & 3) * 128 + m0 + mt * 16 + hh * 8 + gid] = v;
            }
    }
    __syncthreads();

    if (tid < 128) {
        float t = sPart[tid] + sPart[128 + tid] + sPart[256 + tid] + sPart[384 + tid]
                + g_cei;
        sEij[tid] = 1.f / (1.f + __expf(-t));
    }
    __syncthreads();

    // ---- GEMM2: mij = S @ W2 (+b2); scatter directly from registers ----
    zero_c(c);
    warp_gemm32(sb + R1_OFF + aOff2, sb + RW2_OFF + bOff2, LD2 * 2, 8, c);
#pragma unroll
    for (int mt = 0; mt < 2; mt++) {
        int row = m0 + mt * 16 + gid;
        int d0 = sDst[row], d1 = sDst[row + 8];
        float e0v = sEij[row], e1v = sEij[row + 8];
        float* g0 = g_mi + (size_t)d0 * HIDD;
        float* g1 = g_mi + (size_t)d1 * HIDD;
#pragma unroll
        for (int nt = 0; nt < 4; nt++) {
            int col = n0 + nt * 8 + tig * 2;
            float* cc = c[mt][nt];
            float b0 = sB2[col], b1 = sB2[col + 1];
            asm volatile("red.global.add.v2.f32 [%0], {%1,%2};"
                         :: "l"(g0 + col), "f"((cc[0] + b0) * e0v),
                            "f"((cc[1] + b1) * e0v) : "memory");
            asm volatile("red.global.add.v2.f32 [%0], {%1,%2};"
                         :: "l"(g1 + col), "f"((cc[2] + b0) * e1v),
                            "f"((cc[3] + b1) * e1v) : "memory");
        }
    }
    CPA_WAIT0();
    __syncthreads();   // W23t visible to all

    // ---- GEMM3': u_pre = S @ W23; gate partials ----
    zero_c(c);
    warp_gemm32(sb + R1_OFF + aOff2, sb + RW23_OFF + bOff2, LD2 * 2, 8, c);
    {
        float p[2][2] = {{0.f, 0.f}, {0.f, 0.f}};
#pragma unroll
        for (int mt = 0; mt < 2; mt++)
#pragma unroll
            for (int nt = 0; nt < 4; nt++) {
                int col = n0 + nt * 8 + tig * 2;
                float* cc = c[mt][nt];
                p[mt][0] += siluf(cc[0] + sB23[col]) * sXW2[col]
                          + siluf(cc[1] + sB23[col + 1]) * sXW2[col + 1];
                p[mt][1] += siluf(cc[2] + sB23[col]) * sXW2[col]
                          + siluf(cc[3] + sB23[col + 1]) * sXW2[col + 1];
            }
#pragma unroll
        for (int mt = 0; mt < 2; mt++)
#pragma unroll
            for (int hh = 0; hh < 2; hh++) {
                float v = p[mt][hh];
                v += __shfl_xor_sync(0xffffffffu, v, 1);
                v += __shfl_xor_sync(0xffffffffu, v, 2);
                if (tig == 0)
                    sPart[(wid & 3) * 128 + m0 + mt * 16 + hh * 8 + gid] = v;
            }
    }
    __syncthreads();

    if (tid < 128) {
        float g = tanhf(sPart[tid] + sPart[128 + tid] + sPart[256 + tid] + sPart[384 + tid]);
        float coef = g / (sqrtf(sDsq[tid] + 1e-8f) + 1.f);
        int d = sDst[tid];
        atomicAdd(&x_out[d * 3 + 0], sRlX[tid] * coef);
        atomicAdd(&x_out[d * 3 + 1], sRlY[tid] * coef);
        atomicAdd(&x_out[d * 3 + 2], sRlZ[tid] * coef);
    }
}

// ---------------------------------------------------------------------------
// Node kernel: h_out = h + nm2(silu(mi@nm_w1a + Ph + b1)) + b2
// ---------------------------------------------------------------------------
__global__ void __launch_bounds__(NT, 2) egnn_node_kernel(
    const float* __restrict__ h,
    const float* __restrict__ nm_b1, const float* __restrict__ nm_b2,
    float* __restrict__ h_out)
{
    extern __shared__ unsigned char sm[];
    const uint32_t sb = smem_u32(sm);
    const int tid  = threadIdx.x;
    const int wid  = tid >> 5;
    const int lane = tid & 31;
    const int gid  = lane >> 2;
    const int tig  = lane & 3;
    const int m0   = (wid >> 2) * 32;
    const int n0   = (wid & 3) * 32;
    const int nb   = blockIdx.x * ME;

    float* sB1 = (float*)(sm + 0);
    float* sB2 = (float*)(sm + 512);

    for (int q = tid; q < WBYTES / 16; q += NT)
        cpa16(sb + NW_OFF + q * 16, (const unsigned char*)g_nw1at + q * 16);
    CPA_COMMIT();

    if (tid < 128) { sB1[tid] = nm_b1[tid]; sB2[tid] = nm_b2[tid]; }

    for (int q = tid; q < ME * 16; q += NT) {
        int e = q >> 4, ch = q & 15;
        int n = nb + e;
        uint4 w = make_uint4(0, 0, 0, 0);
        if (n < NN) {
            const float4* sp = (const float4*)(g_mi + (size_t)n * HIDD + ch * 8);
            float4 v0 = sp[0], v1 = sp[1];
            w.x = pk(v0.x, v0.y); w.y = pk(v0.z, v0.w);
            w.z = pk(v1.x, v1.y); w.w = pk(v1.z, v1.w);
        }
        sts128(sb + NA_OFF + (uint32_t)(e * LD2 + ch * 8) * 2, w);
    }
    CPA_WAIT0();
    __syncthreads();

    const uint32_t aOff = (uint32_t)(m0 + (lane & 15)) * (LD2 * 2) + ((lane >> 4) << 4);
    const uint32_t bOff = (uint32_t)(n0 + (lane & 7) + ((lane >> 4) << 3)) * (LD2 * 2)
                        + (((lane >> 3) & 1) << 4);
    float c[2][4][4];

    zero_c(c);
    warp_gemm32(sb + NA_OFF + aOff, sb + NW_OFF + bOff, LD2 * 2, 8, c);
    __syncthreads();

    for (int q = tid; q < WBYTES / 16; q += NT)
        cpa16(sb + NW_OFF + q * 16, (const unsigned char*)g_nw2t + q * 16);
    CPA_COMMIT();

#pragma unroll
    for (int mt = 0; mt < 2; mt++)
#pragma unroll
        for (int nt = 0; nt < 4; nt++) {
            int row = m0 + mt * 16 + gid;
            int col = n0 + nt * 8 + tig * 2;
            float* cc = c[mt][nt];
            int na = nb + row, na2 = nb + row + 8;
            float2 p0 = make_float2(0.f, 0.f), p1 = make_float2(0.f, 0.f);
            if (na < NN) {
                uint32_t pv = g_ph16[(size_t)na * 64 + (col >> 1)];
                p0 = make_float2(ubf_lo(pv), ubf_hi(pv));
            }
            if (na2 < NN) {
                uint32_t pv = g_ph16[(size_t)na2 * 64 + (col >> 1)];
                p1 = make_float2(ubf_lo(pv), ubf_hi(pv));
            }
            sts32(sb + NA_OFF + (uint32_t)(row * LD2 + col) * 2,
                  pk(siluf(cc[0] + p0.x + sB1[col]), siluf(cc[1] + p0.y + sB1[col + 1])));
            sts32(sb + NA_OFF + (uint32_t)((row + 8) * LD2 + col) * 2,
                  pk(siluf(cc[2] + p1.x + sB1[col]), siluf(cc[3] + p1.y + sB1[col + 1])));
        }
    CPA_WAIT0();
    __syncthreads();

    zero_c(c);
    warp_gemm32(sb + NA_OFF + aOff, sb + NW_OFF + bOff, LD2 * 2, 8, c);

#pragma unroll
    for (int mt = 0; mt < 2; mt++)
#pragma unroll
        for (int nt = 0; nt < 4; nt++) {
            int row = m0 + mt * 16 + gid;
            int col = n0 + nt * 8 + tig * 2;
            float* cc = c[mt][nt];
            int na = nb + row, na2 = nb + row + 8;
            if (na < NN) {
                const float2 hv = *(const float2*)(h + (size_t)na * HIDD + col);
                *(float2*)(h_out + (size_t)na * HIDD + col) =
                    make_float2(cc[0] + sB2[col] + hv.x, cc[1] + sB2[col + 1] + hv.y);
            }
            if (na2 < NN) {
                const float2 hv = *(const float2*)(h + (size_t)na2 * HIDD + col);
                *(float2*)(h_out + (size_t)na2 * HIDD + col) =
                    make_float2(cc[2] + sB2[col] + hv.x, cc[3] + sB2[col + 1] + hv.y);
            }
        }
}

// ---------------------------------------------------------------------------
extern "C" void kernel_launch(void* const* d_in, const int* in_sizes, int n_in,
                              void* d_out, int out_size) {
    const float* h     = (const float*)d_in[0];
    const float* x     = (const float*)d_in[1];
    const int*   eidx  = (const int*)  d_in[2];
    const float* eattr = (const float*)d_in[3];
    const float* em_w1 = (const float*)d_in[4];
    const float* em_b1 = (const float*)d_in[5];
    const float* em_w2 = (const float*)d_in[6];
    const float* em_b2 = (const float*)d_in[7];
    const float* ei_w  = (const float*)d_in[8];
    const float* ei_b  = (const float*)d_in[9];
    const float* xm_w1 = (const float*)d_in[10];
    const float* xm_b1 = (const float*)d_in[11];
    const float* xm_w2 = (const float*)d_in[12];
    const float* nm_w1 = (const float*)d_in[13];
    const float* nm_b1 = (const float*)d_in[14];
    const float* nm_w2 = (const float*)d_in[15];
    const float* nm_b2 = (const float*)d_in[16];

    float* out   = (float*)d_out;
    float* h_out = out;                        // [NN, 128]
    float* x_out = out + (size_t)NN * HIDD;    // [NN, 3]

    cudaFuncSetAttribute(egnn_edge_kernel,
                         cudaFuncAttributeMaxDynamicSharedMemorySize, EDGE_SMEM);
    cudaFuncSetAttribute(egnn_node_kernel,
                         cudaFuncAttributeMaxDynamicSharedMemorySize, NODE_SMEM);
    cudaFuncSetAttribute(egnn_pre_kernel,
                         cudaFuncAttributeMaxDynamicSharedMemorySize, NODE_SMEM);

    egnn_prep_kernel<<<592, 256>>>(em_w1, em_w2, xm_w1, nm_w1, nm_w2,
                                   em_b1, em_b2, ei_w, ei_b, xm_b1, x, x_out);
    egnn_pre_kernel<<<(NN + ME - 1) / ME, NT, NODE_SMEM>>>(h);
    egnn_edge_kernel<<<NE / ME, NT, EDGE_SMEM>>>(
        x, eidx, eattr, em_b2, xm_w2, x_out);
    egnn_node_kernel<<<(NN + ME - 1) / ME, NT, NODE_SMEM>>>(
        h, nm_b1, nm_b2, h_out);
}